// round 2
// baseline (speedup 1.0000x reference)
#include <cuda_runtime.h>
#include <math.h>

// Problem constants
#define NN 1024   // nodes
#define BB 64     // batch
#define TT 12     // time steps
#define DD 16     // embedding dim
#define HH 64     // hidden
#define CC 65     // C_IN + H
#define LCOLS (BB*CC)   // 4160
#define OG 128    // gate output (2H)
#define OU 64     // update output (H)

// ---------------- scratch (static device allocations) ----------------
__device__ float d_ne_g[TT*NN*DD];
__device__ float d_ne_u[TT*NN*DD];
__device__ float d_Sg[(size_t)TT*NN*NN];   // 48 MB
__device__ float d_Su[(size_t)TT*NN*NN];   // 48 MB
__device__ float d_h [NN*BB*HH];           // [N,B,H]
__device__ float d_r [NN*BB*HH];
__device__ float d_Xg [(size_t)NN*LCOLS];  // [N, B*65]
__device__ float d_Y1g[(size_t)NN*LCOLS];
__device__ float d_Y2g[(size_t)NN*LCOLS];
__device__ float d_Xu [(size_t)NN*LCOLS];
__device__ float d_Y1u[(size_t)NN*LCOLS];
__device__ float d_Y2u[(size_t)NN*LCOLS];

// ---------------- h = 0 ----------------
__global__ void zero_h_kernel()
{
    int i = blockIdx.x*blockDim.x + threadIdx.x;
    if (i < NN*BB*HH) d_h[i] = 0.f;
}

// ---------------- layernormed node+time embeddings, all t ----------------
__global__ void compute_ne_kernel(const float* __restrict__ nodeE,
                                  const float* __restrict__ timeE,
                                  const float* __restrict__ gg, const float* __restrict__ gbeta,
                                  const float* __restrict__ ug, const float* __restrict__ ubeta)
{
    int idx = blockIdx.x*blockDim.x + threadIdx.x;   // t*NN + n
    if (idx >= TT*NN) return;
    int t = idx >> 10;
    int n = idx & (NN-1);
    float v[DD];
    float mu = 0.f;
#pragma unroll
    for (int d = 0; d < DD; d++) { v[d] = nodeE[n*DD+d] + timeE[t*DD+d]; mu += v[d]; }
    mu *= (1.f/DD);
    float var = 0.f;
#pragma unroll
    for (int d = 0; d < DD; d++) { float dv = v[d]-mu; var += dv*dv; }
    var *= (1.f/DD);
    float inv = 1.f / sqrtf(var + 1e-12f);
#pragma unroll
    for (int d = 0; d < DD; d++) {
        float nv = (v[d]-mu)*inv;
        d_ne_g[idx*DD+d] = nv*gg[d] + gbeta[d];
        d_ne_u[idx*DD+d] = nv*ug[d] + ubeta[d];
    }
}

// ---------------- adaptive adjacency S = softmax(ne @ ne^T), row-wise ----------------
__global__ __launch_bounds__(256) void compute_S_kernel(int which)
{
    const float* ne = which ? d_ne_u : d_ne_g;
    float* S        = which ? d_Su   : d_Sg;
    int n = blockIdx.x, t = blockIdx.y;
    int tid = threadIdx.x;
    const float* net = ne + t*NN*DD;
    __shared__ float buf[NN];
    __shared__ float red[256];
    float ner[DD];
#pragma unroll
    for (int d = 0; d < DD; d++) ner[d] = net[n*DD+d];
    float lmax = -1e30f;
    for (int j = tid; j < NN; j += 256) {
        const float* p = net + j*DD;
        float s = 0.f;
#pragma unroll
        for (int d = 0; d < DD; d++) s += ner[d]*p[d];
        buf[j] = s;
        lmax = fmaxf(lmax, s);
    }
    red[tid] = lmax; __syncthreads();
    for (int o = 128; o > 0; o >>= 1) { if (tid < o) red[tid] = fmaxf(red[tid], red[tid+o]); __syncthreads(); }
    float mx = red[0]; __syncthreads();
    float lsum = 0.f;
    for (int j = tid; j < NN; j += 256) { float e = expf(buf[j]-mx); buf[j] = e; lsum += e; }
    red[tid] = lsum; __syncthreads();
    for (int o = 128; o > 0; o >>= 1) { if (tid < o) red[tid] += red[tid+o]; __syncthreads(); }
    float inv = 1.f / red[0];
    float* Srow = S + ((size_t)(t*NN + n))*NN;
    for (int j = tid; j < NN; j += 256) Srow[j] = buf[j]*inv;
}

// ---------------- pack Xg = cat[x_t, h] into [N, B*65] ----------------
__global__ void pack_Xg_kernel(const float* __restrict__ x, int t)
{
    int idx = blockIdx.x*blockDim.x + threadIdx.x;
    if (idx >= NN*LCOLS) return;
    int n   = idx / LCOLS;
    int rem = idx - n*LCOLS;
    int b   = rem / CC;
    int c   = rem - b*CC;
    float v;
    if (c == 0) v = x[(b*TT + t)*NN + n];
    else        v = d_h[(n*BB + b)*HH + (c-1)];
    d_Xg[idx] = v;
}

// ---------------- SGEMM: C[1024,4160] = S[1024,1024] @ B[1024,4160] ----------------
__device__ __forceinline__ const float* gemm_src(int id)
{
    switch (id) {
        case 0: return d_Xg;  case 1: return d_Y1g; case 2: return d_Y2g;
        case 3: return d_Xu;  case 4: return d_Y1u; default: return d_Y2u;
    }
}
__device__ __forceinline__ float* gemm_dst(int id)
{
    switch (id) {
        case 1: return d_Y1g; case 2: return d_Y2g;
        case 4: return d_Y1u; default: return d_Y2u;
    }
}

__global__ __launch_bounds__(256) void sgemm_kernel(int su, int t, int bsel, int csel)
{
    const int K = NN, L = LCOLS;
    const float* __restrict__ A = (su ? d_Su : d_Sg) + (size_t)t*NN*NN;
    const float* __restrict__ B = gemm_src(bsel);
    float* __restrict__ C = gemm_dst(csel);
    __shared__ float As[8][128];   // transposed A tile
    __shared__ float Bs[8][128];
    int tid = threadIdx.x;
    int trow = (tid >> 4) << 3;    // 0..120
    int tcol = (tid & 15) << 3;    // 0..120
    int aRow = tid >> 1;           // 0..127
    int aCol = (tid & 1) << 2;     // 0 or 4
    int bRow = tid >> 5;           // 0..7
    int bCol = (tid & 31) << 2;    // 0..124
    const float* Ap = A + (size_t)(blockIdx.y*128 + aRow)*K + aCol;
    int gcol = blockIdx.x*128 + bCol;
    const float* Bp = B + (size_t)bRow*L + gcol;
    bool bok = gcol < L;           // L multiple of 4 -> group all-in or all-out
    float acc[8][8];
#pragma unroll
    for (int i = 0; i < 8; i++)
#pragma unroll
        for (int j = 0; j < 8; j++) acc[i][j] = 0.f;

    for (int k0 = 0; k0 < K; k0 += 8) {
        float4 a4 = *(const float4*)(Ap + k0);
        As[aCol+0][aRow] = a4.x; As[aCol+1][aRow] = a4.y;
        As[aCol+2][aRow] = a4.z; As[aCol+3][aRow] = a4.w;
        float4 b4 = make_float4(0.f, 0.f, 0.f, 0.f);
        if (bok) b4 = *(const float4*)(Bp + (size_t)k0*L);
        *(float4*)&Bs[bRow][bCol] = b4;
        __syncthreads();
#pragma unroll
        for (int kk = 0; kk < 8; kk++) {
            float ar[8], br[8];
            *(float4*)&ar[0] = *(const float4*)&As[kk][trow];
            *(float4*)&ar[4] = *(const float4*)&As[kk][trow+4];
            *(float4*)&br[0] = *(const float4*)&Bs[kk][tcol];
            *(float4*)&br[4] = *(const float4*)&Bs[kk][tcol+4];
#pragma unroll
            for (int i = 0; i < 8; i++)
#pragma unroll
                for (int j = 0; j < 8; j++) acc[i][j] += ar[i]*br[j];
        }
        __syncthreads();
    }
    int col0 = blockIdx.x*128 + tcol;   // multiple of 8; L multiple of 8
    if (col0 < L) {
#pragma unroll
        for (int i = 0; i < 8; i++) {
            float* cp = C + (size_t)(blockIdx.y*128 + trow + i)*L + col0;
            *(float4*)cp     = make_float4(acc[i][0], acc[i][1], acc[i][2], acc[i][3]);
            *(float4*)(cp+4) = make_float4(acc[i][4], acc[i][5], acc[i][6], acc[i][7]);
        }
    }
}

// ---------------- gate GCN epilogue: sigmoid, split z/r, build Xu ----------------
__global__ __launch_bounds__(256) void gate_epi_kernel(
    const float* __restrict__ gW, const float* __restrict__ gb,
    const float* __restrict__ x, int t)
{
    __shared__ float Wn[CC*64];    // per-node filter, one 64-wide output half
    __shared__ float xgs[BB*CC];   // one support's mixed features for node n
    int n = blockIdx.x;
    int tid = threadIdx.x;
    int to = tid & 15, tb = tid >> 4;
    int ob4 = to << 2;
    const float* ne = d_ne_g + (t*NN + n)*DD;
    float ner[DD];
#pragma unroll
    for (int d = 0; d < DD; d++) ner[d] = ne[d];

    for (int half = 0; half < 2; half++) {   // half 0 = z, half 1 = r
        int obase = half*64;
        float acc[4][4];
#pragma unroll
        for (int j = 0; j < 4; j++) {
            float s = 0.f;
#pragma unroll
            for (int d = 0; d < DD; d++) s += ner[d]*gb[d*OG + obase + ob4 + j];
#pragma unroll
            for (int i = 0; i < 4; i++) acc[i][j] = s;
        }
        for (int k = 0; k < 3; k++) {
            __syncthreads();
            for (int idx = tid; idx < CC*64; idx += 256) {
                int i = idx >> 6, oo = idx & 63;
                float s = 0.f;
#pragma unroll
                for (int d = 0; d < DD; d++)
                    s += ner[d]*gW[((size_t)(d*3+k)*CC + i)*OG + obase + oo];
                Wn[idx] = s;
            }
            const float* row = (k==0 ? d_Xg : (k==1 ? d_Y1g : d_Y2g)) + (size_t)n*LCOLS;
            if (k < 2) {
                for (int idx = tid; idx < LCOLS; idx += 256) xgs[idx] = row[idx];
            } else {   // support_2 = 2*S^2 - I  ->  2*Y2 - X
                const float* xr = d_Xg + (size_t)n*LCOLS;
                for (int idx = tid; idx < LCOLS; idx += 256) xgs[idx] = 2.f*row[idx] - xr[idx];
            }
            __syncthreads();
            for (int i = 0; i < CC; i++) {
                float4 wv = *(const float4*)&Wn[i*64 + ob4];
#pragma unroll
                for (int bb = 0; bb < 4; bb++) {
                    float xv = xgs[(tb*4+bb)*CC + i];
                    acc[bb][0] += xv*wv.x; acc[bb][1] += xv*wv.y;
                    acc[bb][2] += xv*wv.z; acc[bb][3] += xv*wv.w;
                }
            }
        }
        // finalize
#pragma unroll
        for (int bb = 0; bb < 4; bb++) {
            int b = tb*4 + bb;
#pragma unroll
            for (int j = 0; j < 4; j++) {
                float v = 1.f/(1.f + expf(-acc[bb][j]));
                int o = ob4 + j;
                if (half == 0) {
                    float hv = d_h[(n*BB + b)*HH + o];
                    d_Xu[(size_t)n*LCOLS + b*CC + 1 + o] = v*hv;   // z * state
                } else {
                    d_r[(n*BB + b)*HH + o] = v;                    // r
                }
            }
            if (half == 0 && to == 0)
                d_Xu[(size_t)n*LCOLS + b*CC] = x[(b*TT + t)*NN + n];  // x_t channel
        }
    }
}

// ---------------- update GCN epilogue: tanh, GRU combine, write h + out ----------------
__global__ __launch_bounds__(256) void update_epi_kernel(
    const float* __restrict__ uW, const float* __restrict__ ub,
    float* __restrict__ out, int t)
{
    __shared__ float Wn[CC*64];
    __shared__ float xgs[BB*CC];
    int n = blockIdx.x;
    int tid = threadIdx.x;
    int to = tid & 15, tb = tid >> 4;
    int ob4 = to << 2;
    const float* ne = d_ne_u + (t*NN + n)*DD;
    float ner[DD];
#pragma unroll
    for (int d = 0; d < DD; d++) ner[d] = ne[d];

    float acc[4][4];
#pragma unroll
    for (int j = 0; j < 4; j++) {
        float s = 0.f;
#pragma unroll
        for (int d = 0; d < DD; d++) s += ner[d]*ub[d*OU + ob4 + j];
#pragma unroll
        for (int i = 0; i < 4; i++) acc[i][j] = s;
    }
    for (int k = 0; k < 3; k++) {
        __syncthreads();
        for (int idx = tid; idx < CC*64; idx += 256) {
            int i = idx >> 6, oo = idx & 63;
            float s = 0.f;
#pragma unroll
            for (int d = 0; d < DD; d++)
                s += ner[d]*uW[((size_t)(d*3+k)*CC + i)*OU + oo];
            Wn[idx] = s;
        }
        const float* row = (k==0 ? d_Xu : (k==1 ? d_Y1u : d_Y2u)) + (size_t)n*LCOLS;
        if (k < 2) {
            for (int idx = tid; idx < LCOLS; idx += 256) xgs[idx] = row[idx];
        } else {
            const float* xr = d_Xu + (size_t)n*LCOLS;
            for (int idx = tid; idx < LCOLS; idx += 256) xgs[idx] = 2.f*row[idx] - xr[idx];
        }
        __syncthreads();
        for (int i = 0; i < CC; i++) {
            float4 wv = *(const float4*)&Wn[i*64 + ob4];
#pragma unroll
            for (int bb = 0; bb < 4; bb++) {
                float xv = xgs[(tb*4+bb)*CC + i];
                acc[bb][0] += xv*wv.x; acc[bb][1] += xv*wv.y;
                acc[bb][2] += xv*wv.z; acc[bb][3] += xv*wv.w;
            }
        }
    }
    // GRU combine: h = r*h + (1-r)*tanh(candidate)
#pragma unroll
    for (int bb = 0; bb < 4; bb++) {
        int b = tb*4 + bb;
#pragma unroll
        for (int j = 0; j < 4; j++) {
            int o = ob4 + j;
            float hc = tanhf(acc[bb][j]);
            int hidx = (n*BB + b)*HH + o;
            float hv = d_h[hidx];
            float rv = d_r[hidx];
            float hn = rv*hv + (1.f - rv)*hc;
            d_h[hidx] = hn;
            out[((size_t)(b*TT + t)*NN + n)*HH + o] = hn;
        }
    }
}

// ---------------- host launcher ----------------
extern "C" void kernel_launch(void* const* d_in, const int* in_sizes, int n_in,
                              void* d_out, int out_size)
{
    const float *x = nullptr, *nodeE = nullptr, *timeE = nullptr;
    const float *gW = nullptr, *gb = nullptr, *uW = nullptr, *ub = nullptr;
    const float *ln16[4] = {nullptr, nullptr, nullptr, nullptr};
    int nln = 0;
    for (int i = 0; i < n_in; i++) {
        const float* p = (const float*)d_in[i];
        switch (in_sizes[i]) {
            case 786432: x = p; break;      // [64,12,1024,1]
            case 16384:  nodeE = p; break;  // [1024,16]
            case 192:    timeE = p; break;  // [12,16]
            case 399360: gW = p; break;     // [16,3,65,128]
            case 2048:   gb = p; break;     // [16,128]
            case 199680: uW = p; break;     // [16,3,65,64]
            case 1024:   ub = p; break;     // [16,64]
            case 16:     if (nln < 4) ln16[nln++] = p; break;
            default: break;
        }
    }
    const float* glg = ln16[0]; const float* glb = ln16[1];
    const float* ulg = ln16[2]; const float* ulb = ln16[3];
    float* out = (float*)d_out;

    zero_h_kernel<<<(NN*BB*HH + 255)/256, 256>>>();
    compute_ne_kernel<<<(TT*NN + 255)/256, 256>>>(nodeE, timeE, glg, glb, ulg, ulb);
    compute_S_kernel<<<dim3(NN, TT), 256>>>(0);
    compute_S_kernel<<<dim3(NN, TT), 256>>>(1);

    dim3 ggrid((LCOLS + 127)/128, NN/128);   // (33, 8)
    for (int t = 0; t < TT; t++) {
        pack_Xg_kernel<<<((size_t)NN*LCOLS + 255)/256, 256>>>(x, t);
        sgemm_kernel<<<ggrid, 256>>>(0, t, 0, 1);   // Y1g = Sg @ Xg
        sgemm_kernel<<<ggrid, 256>>>(0, t, 1, 2);   // Y2g = Sg @ Y1g
        gate_epi_kernel<<<NN, 256>>>(gW, gb, x, t); // -> Xu, r
        sgemm_kernel<<<ggrid, 256>>>(1, t, 3, 4);   // Y1u = Su @ Xu
        sgemm_kernel<<<ggrid, 256>>>(1, t, 4, 5);   // Y2u = Su @ Y1u
        update_epi_kernel<<<NN, 256>>>(uW, ub, out, t); // -> h, out[:,t]
    }
}

// round 4
// speedup vs baseline: 1.7926x; 1.7926x over previous
#include <cuda_runtime.h>
#include <cuda_bf16.h>
#include <math.h>

// Problem constants
#define NN 1024   // nodes
#define BB 64     // batch
#define TT 12     // time steps
#define DD 16     // embedding dim
#define HH 64     // hidden
#define CC 65     // C_IN + H
#define LCOLS (BB*CC)   // 4160
#define OG 128    // gate output (2H)
#define OU 64     // update output (H)

// ---------------- scratch (static device allocations) ----------------
__device__ float d_ne_g[TT*NN*DD];
__device__ float d_ne_u[TT*NN*DD];
__device__ float d_Sg[(size_t)TT*NN*NN];   // 48 MB
__device__ float d_Su[(size_t)TT*NN*NN];   // 48 MB
__device__ float d_h [NN*BB*HH];           // [N,B,H]
__device__ float d_r [NN*BB*HH];
__device__ float d_Xg [(size_t)NN*LCOLS];  // [N, B*65]
__device__ float d_Y1g[(size_t)NN*LCOLS];
__device__ float d_Y2g[(size_t)NN*LCOLS];
__device__ float d_Xu [(size_t)NN*LCOLS];
__device__ float d_Y1u[(size_t)NN*LCOLS];
__device__ float d_Y2u[(size_t)NN*LCOLS];

// ---------------- h = 0 ----------------
__global__ void zero_h_kernel()
{
    int i = blockIdx.x*blockDim.x + threadIdx.x;
    if (i < NN*BB*HH) d_h[i] = 0.f;
}

// ---------------- layernormed node+time embeddings, all t ----------------
__global__ void compute_ne_kernel(const float* __restrict__ nodeE,
                                  const float* __restrict__ timeE,
                                  const float* __restrict__ gg, const float* __restrict__ gbeta,
                                  const float* __restrict__ ug, const float* __restrict__ ubeta)
{
    int idx = blockIdx.x*blockDim.x + threadIdx.x;   // t*NN + n
    if (idx >= TT*NN) return;
    int t = idx >> 10;
    int n = idx & (NN-1);
    float v[DD];
    float mu = 0.f;
#pragma unroll
    for (int d = 0; d < DD; d++) { v[d] = nodeE[n*DD+d] + timeE[t*DD+d]; mu += v[d]; }
    mu *= (1.f/DD);
    float var = 0.f;
#pragma unroll
    for (int d = 0; d < DD; d++) { float dv = v[d]-mu; var += dv*dv; }
    var *= (1.f/DD);
    float inv = 1.f / sqrtf(var + 1e-12f);
#pragma unroll
    for (int d = 0; d < DD; d++) {
        float nv = (v[d]-mu)*inv;
        d_ne_g[idx*DD+d] = nv*gg[d] + gbeta[d];
        d_ne_u[idx*DD+d] = nv*ug[d] + ubeta[d];
    }
}

// ---------------- scores G = ne @ ne^T  (written into d_Sg/d_Su) ----------------
__global__ __launch_bounds__(256) void score_kernel()
{
    int z = blockIdx.z;
    int which = (z >= TT) ? 1 : 0;
    int t = which ? (z - TT) : z;
    const float* __restrict__ ne = (which ? d_ne_u : d_ne_g) + t*NN*DD;
    float* __restrict__ G = (which ? d_Su : d_Sg) + (size_t)t*NN*NN;
    __shared__ float Rt[DD][132];
    __shared__ float Ct[DD][132];
    int tid = threadIdx.x;
#pragma unroll
    for (int rep = 0; rep < 2; rep++) {
        int f = tid + rep*256;
        int r = f >> 2, q = (f & 3) << 2;
        float4 v = *(const float4*)(ne + (blockIdx.y*128 + r)*DD + q);
        Rt[q+0][r] = v.x; Rt[q+1][r] = v.y; Rt[q+2][r] = v.z; Rt[q+3][r] = v.w;
        float4 w = *(const float4*)(ne + (blockIdx.x*128 + r)*DD + q);
        Ct[q+0][r] = w.x; Ct[q+1][r] = w.y; Ct[q+2][r] = w.z; Ct[q+3][r] = w.w;
    }
    __syncthreads();
    int ty = tid >> 4, tx = tid & 15;
    int r0 = ty*8, c0 = tx*8;
    float acc[8][8];
#pragma unroll
    for (int i = 0; i < 8; i++)
#pragma unroll
        for (int j = 0; j < 8; j++) acc[i][j] = 0.f;
#pragma unroll
    for (int k = 0; k < DD; k++) {
        float rv[8], cv[8];
        *(float4*)&rv[0] = *(const float4*)&Rt[k][r0];
        *(float4*)&rv[4] = *(const float4*)&Rt[k][r0+4];
        *(float4*)&cv[0] = *(const float4*)&Ct[k][c0];
        *(float4*)&cv[4] = *(const float4*)&Ct[k][c0+4];
#pragma unroll
        for (int i = 0; i < 8; i++)
#pragma unroll
            for (int j = 0; j < 8; j++) acc[i][j] += rv[i]*cv[j];
    }
#pragma unroll
    for (int i = 0; i < 8; i++) {
        float* gp = G + (size_t)(blockIdx.y*128 + r0 + i)*NN + blockIdx.x*128 + c0;
        *(float4*)gp     = make_float4(acc[i][0], acc[i][1], acc[i][2], acc[i][3]);
        *(float4*)(gp+4) = make_float4(acc[i][4], acc[i][5], acc[i][6], acc[i][7]);
    }
}

// ---------------- row softmax in place (warp per row) ----------------
__global__ __launch_bounds__(256) void softmax_kernel()
{
    int which = blockIdx.z, t = blockIdx.y;
    float* S = (which ? d_Su : d_Sg) + (size_t)t*NN*NN;
    int warp = threadIdx.x >> 5, lane = threadIdx.x & 31;
    int row = blockIdx.x*8 + warp;
    float4* p = (float4*)(S + (size_t)row*NN);
    float4 v[8];
    float mx = -1e30f;
#pragma unroll
    for (int i = 0; i < 8; i++) {
        v[i] = p[lane + i*32];
        mx = fmaxf(mx, fmaxf(fmaxf(v[i].x, v[i].y), fmaxf(v[i].z, v[i].w)));
    }
#pragma unroll
    for (int o = 16; o > 0; o >>= 1) mx = fmaxf(mx, __shfl_xor_sync(0xffffffffu, mx, o));
    float sum = 0.f;
#pragma unroll
    for (int i = 0; i < 8; i++) {
        v[i].x = __expf(v[i].x - mx); v[i].y = __expf(v[i].y - mx);
        v[i].z = __expf(v[i].z - mx); v[i].w = __expf(v[i].w - mx);
        sum += v[i].x + v[i].y + v[i].z + v[i].w;
    }
#pragma unroll
    for (int o = 16; o > 0; o >>= 1) sum += __shfl_xor_sync(0xffffffffu, sum, o);
    float inv = 1.f / sum;
#pragma unroll
    for (int i = 0; i < 8; i++) {
        v[i].x *= inv; v[i].y *= inv; v[i].z *= inv; v[i].w *= inv;
        p[lane + i*32] = v[i];
    }
}

// ---------------- pack Xg = cat[x_t, h] into [N, B*65] ----------------
__global__ void pack_Xg_kernel(const float* __restrict__ x, int t)
{
    int idx = blockIdx.x*blockDim.x + threadIdx.x;
    if (idx >= NN*LCOLS) return;
    int n   = idx / LCOLS;
    int rem = idx - n*LCOLS;
    int b   = rem / CC;
    int c   = rem - b*CC;
    float v;
    if (c == 0) v = x[(b*TT + t)*NN + n];
    else        v = d_h[(n*BB + b)*HH + (c-1)];
    d_Xg[idx] = v;
}

// ---------------- bf16x3 tensor-core GEMM: C[1024,4160] = S @ B ----------------
__device__ __forceinline__ const float* gemm_src(int id)
{
    switch (id) {
        case 0: return d_Xg;  case 1: return d_Y1g; case 2: return d_Y2g;
        case 3: return d_Xu;  case 4: return d_Y1u; default: return d_Y2u;
    }
}
__device__ __forceinline__ float* gemm_dst(int id)
{
    switch (id) {
        case 1: return d_Y1g; case 2: return d_Y2g;
        case 4: return d_Y1u; default: return d_Y2u;
    }
}

// split two floats into packed bf16x2 hi and lo words
__device__ __forceinline__ void bfsplit2(float x0, float x1, unsigned& hi, unsigned& lo)
{
    __nv_bfloat16 h0 = __float2bfloat16(x0);
    __nv_bfloat16 h1 = __float2bfloat16(x1);
    __nv_bfloat16 l0 = __float2bfloat16(x0 - __bfloat162float(h0));
    __nv_bfloat16 l1 = __float2bfloat16(x1 - __bfloat162float(h1));
    hi = ((unsigned)__bfloat16_as_ushort(h1) << 16) | (unsigned)__bfloat16_as_ushort(h0);
    lo = ((unsigned)__bfloat16_as_ushort(l1) << 16) | (unsigned)__bfloat16_as_ushort(l0);
}

__device__ __forceinline__ void mma_bf16(float& c0, float& c1, float& c2, float& c3,
    unsigned a0, unsigned a1, unsigned a2, unsigned a3, unsigned b0, unsigned b1)
{
    asm volatile("mma.sync.aligned.m16n8k16.row.col.f32.bf16.bf16.f32 "
        "{%0,%1,%2,%3}, {%4,%5,%6,%7}, {%8,%9}, {%0,%1,%2,%3};\n"
        : "+f"(c0), "+f"(c1), "+f"(c2), "+f"(c3)
        : "r"(a0), "r"(a1), "r"(a2), "r"(a3), "r"(b0), "r"(b1));
}

#define SPAD 136   // uint row stride: conflict-free fragment LDS

__global__ __launch_bounds__(256, 2) void mma_gemm_kernel(int su, int t, int bsel, int csel)
{
    const int K = NN, L = LCOLS;
    const float* __restrict__ A = (su ? d_Su : d_Sg) + (size_t)t*NN*NN;
    const float* __restrict__ B = gemm_src(bsel);
    float* __restrict__ C = gemm_dst(csel);

    // k-pair-major tiles: [k2][col], k2 = k/2, value = bf16x2 (k, k+1)
    __shared__ unsigned Ah[2][8][SPAD], Al[2][8][SPAD];
    __shared__ unsigned Bh[2][8][SPAD], Bl[2][8][SPAD];

    int tid  = threadIdx.x;
    int warp = tid >> 5, lane = tid & 31;
    int wm = (warp >> 2) * 64;   // warp grid 2x4 over 128x128 tile
    int wn = (warp & 3) * 32;
    int grp = lane >> 2, tig = lane & 3;

    // global load mapping
    int aRow = tid >> 2;              // 0..63 (+64 second rep)
    int aKq  = (tid & 3) << 2;        // k offset 0,4,8,12
    int aK2  = (tid & 3) << 1;        // pair row 0,2,4,6
    int bCol = (tid & 31) << 2;       // 0..124
    int bRow2 = tid >> 5;             // pair row 0..7 (global rows 2r, 2r+1)

    const float* Ap0 = A + (size_t)(blockIdx.y*128 + aRow)*K + aKq;
    const float* Ap1 = A + (size_t)(blockIdx.y*128 + aRow + 64)*K + aKq;
    int gcol = blockIdx.x*128 + bCol;
    bool bok = gcol < L;
    const float* Bp0 = B + (size_t)(2*bRow2)*L + gcol;
    const float* Bp1 = B + (size_t)(2*bRow2 + 1)*L + gcol;

    float acc[4][4][4];
#pragma unroll
    for (int i = 0; i < 4; i++)
#pragma unroll
        for (int j = 0; j < 4; j++)
#pragma unroll
            for (int c = 0; c < 4; c++) acc[i][j][c] = 0.f;

    // ---- stage tile 0 ----
    {
        float4 a0 = *(const float4*)Ap0;
        float4 a1 = *(const float4*)Ap1;
        float4 b0 = bok ? *(const float4*)Bp0 : make_float4(0,0,0,0);
        float4 b1 = bok ? *(const float4*)Bp1 : make_float4(0,0,0,0);
        unsigned h, l;
        bfsplit2(a0.x, a0.y, h, l); Ah[0][aK2  ][aRow]    = h; Al[0][aK2  ][aRow]    = l;
        bfsplit2(a0.z, a0.w, h, l); Ah[0][aK2+1][aRow]    = h; Al[0][aK2+1][aRow]    = l;
        bfsplit2(a1.x, a1.y, h, l); Ah[0][aK2  ][aRow+64] = h; Al[0][aK2  ][aRow+64] = l;
        bfsplit2(a1.z, a1.w, h, l); Ah[0][aK2+1][aRow+64] = h; Al[0][aK2+1][aRow+64] = l;
        uint4 uh, ul;
        bfsplit2(b0.x, b1.x, uh.x, ul.x);
        bfsplit2(b0.y, b1.y, uh.y, ul.y);
        bfsplit2(b0.z, b1.z, uh.z, ul.z);
        bfsplit2(b0.w, b1.w, uh.w, ul.w);
        *(uint4*)&Bh[0][bRow2][bCol] = uh;
        *(uint4*)&Bl[0][bRow2][bCol] = ul;
    }
    __syncthreads();

    int buf = 0;
    for (int k0 = 0; k0 < K; k0 += 16) {
        bool pf = (k0 + 16) < K;
        float4 pa0, pa1, pb0, pb1;
        if (pf) {
            pa0 = *(const float4*)(Ap0 + k0 + 16);
            pa1 = *(const float4*)(Ap1 + k0 + 16);
            pb0 = bok ? *(const float4*)(Bp0 + (size_t)(k0 + 16)*L) : make_float4(0,0,0,0);
            pb1 = bok ? *(const float4*)(Bp1 + (size_t)(k0 + 16)*L) : make_float4(0,0,0,0);
        }
        // ---- compute on buf: one k16 slice, 3 bf16 terms ----
        unsigned bh[4][2], bl[4][2];
#pragma unroll
        for (int nt = 0; nt < 4; nt++) {
            int n = wn + nt*8 + grp;
            bh[nt][0] = Bh[buf][tig  ][n];
            bh[nt][1] = Bh[buf][tig+4][n];
            bl[nt][0] = Bl[buf][tig  ][n];
            bl[nt][1] = Bl[buf][tig+4][n];
        }
#pragma unroll
        for (int mt = 0; mt < 4; mt++) {
            int m = wm + mt*16;
            unsigned ah0 = Ah[buf][tig  ][m+grp];
            unsigned ah1 = Ah[buf][tig  ][m+grp+8];
            unsigned ah2 = Ah[buf][tig+4][m+grp];
            unsigned ah3 = Ah[buf][tig+4][m+grp+8];
            unsigned al0 = Al[buf][tig  ][m+grp];
            unsigned al1 = Al[buf][tig  ][m+grp+8];
            unsigned al2 = Al[buf][tig+4][m+grp];
            unsigned al3 = Al[buf][tig+4][m+grp+8];
#pragma unroll
            for (int nt = 0; nt < 4; nt++) {
                mma_bf16(acc[mt][nt][0], acc[mt][nt][1], acc[mt][nt][2], acc[mt][nt][3],
                         ah0, ah1, ah2, ah3, bh[nt][0], bh[nt][1]);
                mma_bf16(acc[mt][nt][0], acc[mt][nt][1], acc[mt][nt][2], acc[mt][nt][3],
                         ah0, ah1, ah2, ah3, bl[nt][0], bl[nt][1]);
                mma_bf16(acc[mt][nt][0], acc[mt][nt][1], acc[mt][nt][2], acc[mt][nt][3],
                         al0, al1, al2, al3, bh[nt][0], bh[nt][1]);
            }
        }
        if (pf) {
            int nb = buf ^ 1;
            unsigned h, l;
            bfsplit2(pa0.x, pa0.y, h, l); Ah[nb][aK2  ][aRow]    = h; Al[nb][aK2  ][aRow]    = l;
            bfsplit2(pa0.z, pa0.w, h, l); Ah[nb][aK2+1][aRow]    = h; Al[nb][aK2+1][aRow]    = l;
            bfsplit2(pa1.x, pa1.y, h, l); Ah[nb][aK2  ][aRow+64] = h; Al[nb][aK2  ][aRow+64] = l;
            bfsplit2(pa1.z, pa1.w, h, l); Ah[nb][aK2+1][aRow+64] = h; Al[nb][aK2+1][aRow+64] = l;
            uint4 uh, ul;
            bfsplit2(pb0.x, pb1.x, uh.x, ul.x);
            bfsplit2(pb0.y, pb1.y, uh.y, ul.y);
            bfsplit2(pb0.z, pb1.z, uh.z, ul.z);
            bfsplit2(pb0.w, pb1.w, uh.w, ul.w);
            *(uint4*)&Bh[nb][bRow2][bCol] = uh;
            *(uint4*)&Bl[nb][bRow2][bCol] = ul;
            __syncthreads();
            buf = nb;
        }
    }

    // epilogue: write C
#pragma unroll
    for (int mt = 0; mt < 4; mt++) {
        int row = blockIdx.y*128 + wm + mt*16 + grp;
#pragma unroll
        for (int nt = 0; nt < 4; nt++) {
            int col = blockIdx.x*128 + wn + nt*8 + tig*2;
            if (col < L) {
                *(float2*)&C[(size_t)row*L + col]     = make_float2(acc[mt][nt][0], acc[mt][nt][1]);
                *(float2*)&C[(size_t)(row+8)*L + col] = make_float2(acc[mt][nt][2], acc[mt][nt][3]);
            }
        }
    }
}

// ---------------- gate GCN epilogue: sigmoid, split z/r, build Xu ----------------
__global__ __launch_bounds__(256) void gate_epi_kernel(
    const float* __restrict__ gW, const float* __restrict__ gb,
    const float* __restrict__ x, int t)
{
    __shared__ float Wn[CC*64];    // per-node filter, one 64-wide output half
    __shared__ float xgs[BB*CC];   // one support's mixed features for node n
    int n = blockIdx.x;
    int tid = threadIdx.x;
    int to = tid & 15, tb = tid >> 4;
    int ob4 = to << 2;
    const float* ne = d_ne_g + (t*NN + n)*DD;
    float ner[DD];
#pragma unroll
    for (int d = 0; d < DD; d++) ner[d] = ne[d];

    for (int half = 0; half < 2; half++) {   // half 0 = z, half 1 = r
        int obase = half*64;
        float acc[4][4];
#pragma unroll
        for (int j = 0; j < 4; j++) {
            float s = 0.f;
#pragma unroll
            for (int d = 0; d < DD; d++) s += ner[d]*gb[d*OG + obase + ob4 + j];
#pragma unroll
            for (int i = 0; i < 4; i++) acc[i][j] = s;
        }
        for (int k = 0; k < 3; k++) {
            __syncthreads();
            for (int idx = tid; idx < CC*64; idx += 256) {
                int i = idx >> 6, oo = idx & 63;
                float s = 0.f;
#pragma unroll
                for (int d = 0; d < DD; d++)
                    s += ner[d]*gW[((size_t)(d*3+k)*CC + i)*OG + obase + oo];
                Wn[idx] = s;
            }
            const float* row = (k==0 ? d_Xg : (k==1 ? d_Y1g : d_Y2g)) + (size_t)n*LCOLS;
            if (k < 2) {
                for (int idx = tid; idx < LCOLS; idx += 256) xgs[idx] = row[idx];
            } else {   // support_2 = 2*S^2 - I  ->  2*Y2 - X
                const float* xr = d_Xg + (size_t)n*LCOLS;
                for (int idx = tid; idx < LCOLS; idx += 256) xgs[idx] = 2.f*row[idx] - xr[idx];
            }
            __syncthreads();
            for (int i = 0; i < CC; i++) {
                float4 wv = *(const float4*)&Wn[i*64 + ob4];
#pragma unroll
                for (int bb = 0; bb < 4; bb++) {
                    float xv = xgs[(tb*4+bb)*CC + i];
                    acc[bb][0] += xv*wv.x; acc[bb][1] += xv*wv.y;
                    acc[bb][2] += xv*wv.z; acc[bb][3] += xv*wv.w;
                }
            }
        }
        // finalize
#pragma unroll
        for (int bb = 0; bb < 4; bb++) {
            int b = tb*4 + bb;
#pragma unroll
            for (int j = 0; j < 4; j++) {
                float v = 1.f/(1.f + expf(-acc[bb][j]));
                int o = ob4 + j;
                if (half == 0) {
                    float hv = d_h[(n*BB + b)*HH + o];
                    d_Xu[(size_t)n*LCOLS + b*CC + 1 + o] = v*hv;   // z * state
                } else {
                    d_r[(n*BB + b)*HH + o] = v;                    // r
                }
            }
            if (half == 0 && to == 0)
                d_Xu[(size_t)n*LCOLS + b*CC] = x[(b*TT + t)*NN + n];  // x_t channel
        }
    }
}

// ---------------- update GCN epilogue: tanh, GRU combine, write h + out ----------------
__global__ __launch_bounds__(256) void update_epi_kernel(
    const float* __restrict__ uW, const float* __restrict__ ub,
    float* __restrict__ out, int t)
{
    __shared__ float Wn[CC*64];
    __shared__ float xgs[BB*CC];
    int n = blockIdx.x;
    int tid = threadIdx.x;
    int to = tid & 15, tb = tid >> 4;
    int ob4 = to << 2;
    const float* ne = d_ne_u + (t*NN + n)*DD;
    float ner[DD];
#pragma unroll
    for (int d = 0; d < DD; d++) ner[d] = ne[d];

    float acc[4][4];
#pragma unroll
    for (int j = 0; j < 4; j++) {
        float s = 0.f;
#pragma unroll
        for (int d = 0; d < DD; d++) s += ner[d]*ub[d*OU + ob4 + j];
#pragma unroll
        for (int i = 0; i < 4; i++) acc[i][j] = s;
    }
    for (int k = 0; k < 3; k++) {
        __syncthreads();
        for (int idx = tid; idx < CC*64; idx += 256) {
            int i = idx >> 6, oo = idx & 63;
            float s = 0.f;
#pragma unroll
            for (int d = 0; d < DD; d++)
                s += ner[d]*uW[((size_t)(d*3+k)*CC + i)*OU + oo];
            Wn[idx] = s;
        }
        const float* row = (k==0 ? d_Xu : (k==1 ? d_Y1u : d_Y2u)) + (size_t)n*LCOLS;
        if (k < 2) {
            for (int idx = tid; idx < LCOLS; idx += 256) xgs[idx] = row[idx];
        } else {
            const float* xr = d_Xu + (size_t)n*LCOLS;
            for (int idx = tid; idx < LCOLS; idx += 256) xgs[idx] = 2.f*row[idx] - xr[idx];
        }
        __syncthreads();
        for (int i = 0; i < CC; i++) {
            float4 wv = *(const float4*)&Wn[i*64 + ob4];
#pragma unroll
            for (int bb = 0; bb < 4; bb++) {
                float xv = xgs[(tb*4+bb)*CC + i];
                acc[bb][0] += xv*wv.x; acc[bb][1] += xv*wv.y;
                acc[bb][2] += xv*wv.z; acc[bb][3] += xv*wv.w;
            }
        }
    }
    // GRU combine: h = r*h + (1-r)*tanh(candidate)
#pragma unroll
    for (int bb = 0; bb < 4; bb++) {
        int b = tb*4 + bb;
#pragma unroll
        for (int j = 0; j < 4; j++) {
            int o = ob4 + j;
            float hc = tanhf(acc[bb][j]);
            int hidx = (n*BB + b)*HH + o;
            float hv = d_h[hidx];
            float rv = d_r[hidx];
            float hn = rv*hv + (1.f - rv)*hc;
            d_h[hidx] = hn;
            out[((size_t)(b*TT + t)*NN + n)*HH + o] = hn;
        }
    }
}

// ---------------- host launcher ----------------
extern "C" void kernel_launch(void* const* d_in, const int* in_sizes, int n_in,
                              void* d_out, int out_size)
{
    const float *x = nullptr, *nodeE = nullptr, *timeE = nullptr;
    const float *gW = nullptr, *gb = nullptr, *uW = nullptr, *ub = nullptr;
    const float *ln16[4] = {nullptr, nullptr, nullptr, nullptr};
    int nln = 0;
    for (int i = 0; i < n_in; i++) {
        const float* p = (const float*)d_in[i];
        switch (in_sizes[i]) {
            case 786432: x = p; break;      // [64,12,1024,1]
            case 16384:  nodeE = p; break;  // [1024,16]
            case 192:    timeE = p; break;  // [12,16]
            case 399360: gW = p; break;     // [16,3,65,128]
            case 2048:   gb = p; break;     // [16,128]
            case 199680: uW = p; break;     // [16,3,65,64]
            case 1024:   ub = p; break;     // [16,64]
            case 16:     if (nln < 4) ln16[nln++] = p; break;
            default: break;
        }
    }
    const float* glg = ln16[0]; const float* glb = ln16[1];
    const float* ulg = ln16[2]; const float* ulb = ln16[3];
    float* out = (float*)d_out;

    zero_h_kernel<<<(NN*BB*HH + 255)/256, 256>>>();
    compute_ne_kernel<<<(TT*NN + 255)/256, 256>>>(nodeE, timeE, glg, glb, ulg, ulb);
    score_kernel<<<dim3(8, 8, 2*TT), 256>>>();
    softmax_kernel<<<dim3(128, TT, 2), 256>>>();

    dim3 ggrid((LCOLS + 127)/128, NN/128);   // (33, 8)
    for (int t = 0; t < TT; t++) {
        pack_Xg_kernel<<<((size_t)NN*LCOLS + 255)/256, 256>>>(x, t);
        mma_gemm_kernel<<<ggrid, 256>>>(0, t, 0, 1);   // Y1g = Sg @ Xg
        mma_gemm_kernel<<<ggrid, 256>>>(0, t, 1, 2);   // Y2g = Sg @ Y1g
        gate_epi_kernel<<<NN, 256>>>(gW, gb, x, t);    // -> Xu, r
        mma_gemm_kernel<<<ggrid, 256>>>(1, t, 3, 4);   // Y1u = Su @ Xu
        mma_gemm_kernel<<<ggrid, 256>>>(1, t, 4, 5);   // Y2u = Su @ Y1u
        update_epi_kernel<<<NN, 256>>>(uW, ub, out, t); // -> h, out[:,t]
    }
}

// round 5
// speedup vs baseline: 1.9381x; 1.0811x over previous
#include <cuda_runtime.h>
#include <cuda_bf16.h>
#include <math.h>

// Problem constants
#define NN 1024   // nodes
#define BB 64     // batch
#define TT 12     // time steps
#define DD 16     // embedding dim
#define HH 64     // hidden
#define CC 65     // C_IN + H
#define LCOLS (BB*CC)   // 4160
#define OG 128    // gate output (2H)
#define OU 64     // update output (H)
#define KEPI 208  // padded epilogue K (3*65 -> 208)

// ---------------- scratch (static device allocations) ----------------
__device__ float d_ne_g[TT*NN*DD];
__device__ float d_ne_u[TT*NN*DD];
__device__ float d_Sg[(size_t)TT*NN*NN];   // scores -> packed bf16 hi/lo after softmax
__device__ float d_Su[(size_t)TT*NN*NN];
__device__ float d_h [NN*BB*HH];           // [N,B,H]
__device__ float d_r [NN*BB*HH];
__device__ float d_Xg [(size_t)NN*LCOLS];  // [N, B*65]
__device__ float d_Y1g[(size_t)NN*LCOLS];
__device__ float d_Y2g[(size_t)NN*LCOLS];
__device__ float d_Xu [(size_t)NN*LCOLS];
__device__ float d_Y1u[(size_t)NN*LCOLS];
__device__ float d_Y2u[(size_t)NN*LCOLS];

// ---------------- helpers ----------------
__device__ __forceinline__ unsigned pack_bf16(float v0, float v1)  // low half = v0
{
    __nv_bfloat162 t = __floats2bfloat162_rn(v0, v1);
    return *(unsigned*)&t;
}
__device__ __forceinline__ void split_pack(float v0, float v1, unsigned& hi, unsigned& lo)
{
    __nv_bfloat16 h0 = __float2bfloat16(v0);
    __nv_bfloat16 h1 = __float2bfloat16(v1);
    float r0 = v0 - __bfloat162float(h0);
    float r1 = v1 - __bfloat162float(h1);
    hi = ((unsigned)__bfloat16_as_ushort(h1) << 16) | (unsigned)__bfloat16_as_ushort(h0);
    lo = pack_bf16(r0, r1);
}
__device__ __forceinline__ void mma_bf16(float& c0, float& c1, float& c2, float& c3,
    unsigned a0, unsigned a1, unsigned a2, unsigned a3, unsigned b0, unsigned b1)
{
    asm volatile("mma.sync.aligned.m16n8k16.row.col.f32.bf16.bf16.f32 "
        "{%0,%1,%2,%3}, {%4,%5,%6,%7}, {%8,%9}, {%0,%1,%2,%3};\n"
        : "+f"(c0), "+f"(c1), "+f"(c2), "+f"(c3)
        : "r"(a0), "r"(a1), "r"(a2), "r"(a3), "r"(b0), "r"(b1));
}

// ---------------- h = 0 ----------------
__global__ void zero_h_kernel()
{
    int i = blockIdx.x*blockDim.x + threadIdx.x;
    if (i < NN*BB*HH) d_h[i] = 0.f;
}

// ---------------- layernormed node+time embeddings, all t ----------------
__global__ void compute_ne_kernel(const float* __restrict__ nodeE,
                                  const float* __restrict__ timeE,
                                  const float* __restrict__ gg, const float* __restrict__ gbeta,
                                  const float* __restrict__ ug, const float* __restrict__ ubeta)
{
    int idx = blockIdx.x*blockDim.x + threadIdx.x;   // t*NN + n
    if (idx >= TT*NN) return;
    int t = idx >> 10;
    int n = idx & (NN-1);
    float v[DD];
    float mu = 0.f;
#pragma unroll
    for (int d = 0; d < DD; d++) { v[d] = nodeE[n*DD+d] + timeE[t*DD+d]; mu += v[d]; }
    mu *= (1.f/DD);
    float var = 0.f;
#pragma unroll
    for (int d = 0; d < DD; d++) { float dv = v[d]-mu; var += dv*dv; }
    var *= (1.f/DD);
    float inv = 1.f / sqrtf(var + 1e-12f);
#pragma unroll
    for (int d = 0; d < DD; d++) {
        float nv = (v[d]-mu)*inv;
        d_ne_g[idx*DD+d] = nv*gg[d] + gbeta[d];
        d_ne_u[idx*DD+d] = nv*ug[d] + ubeta[d];
    }
}

// ---------------- scores G = ne @ ne^T  (fp32, written into d_Sg/d_Su) ----------------
__global__ __launch_bounds__(256) void score_kernel()
{
    int z = blockIdx.z;
    int which = (z >= TT) ? 1 : 0;
    int t = which ? (z - TT) : z;
    const float* __restrict__ ne = (which ? d_ne_u : d_ne_g) + t*NN*DD;
    float* __restrict__ G = (which ? d_Su : d_Sg) + (size_t)t*NN*NN;
    __shared__ float Rt[DD][132];
    __shared__ float Ct[DD][132];
    int tid = threadIdx.x;
#pragma unroll
    for (int rep = 0; rep < 2; rep++) {
        int f = tid + rep*256;
        int r = f >> 2, q = (f & 3) << 2;
        float4 v = *(const float4*)(ne + (blockIdx.y*128 + r)*DD + q);
        Rt[q+0][r] = v.x; Rt[q+1][r] = v.y; Rt[q+2][r] = v.z; Rt[q+3][r] = v.w;
        float4 w = *(const float4*)(ne + (blockIdx.x*128 + r)*DD + q);
        Ct[q+0][r] = w.x; Ct[q+1][r] = w.y; Ct[q+2][r] = w.z; Ct[q+3][r] = w.w;
    }
    __syncthreads();
    int ty = tid >> 4, tx = tid & 15;
    int r0 = ty*8, c0 = tx*8;
    float acc[8][8];
#pragma unroll
    for (int i = 0; i < 8; i++)
#pragma unroll
        for (int j = 0; j < 8; j++) acc[i][j] = 0.f;
#pragma unroll
    for (int k = 0; k < DD; k++) {
        float rv[8], cv[8];
        *(float4*)&rv[0] = *(const float4*)&Rt[k][r0];
        *(float4*)&rv[4] = *(const float4*)&Rt[k][r0+4];
        *(float4*)&cv[0] = *(const float4*)&Ct[k][c0];
        *(float4*)&cv[4] = *(const float4*)&Ct[k][c0+4];
#pragma unroll
        for (int i = 0; i < 8; i++)
#pragma unroll
            for (int j = 0; j < 8; j++) acc[i][j] += rv[i]*cv[j];
    }
#pragma unroll
    for (int i = 0; i < 8; i++) {
        float* gp = G + (size_t)(blockIdx.y*128 + r0 + i)*NN + blockIdx.x*128 + c0;
        *(float4*)gp     = make_float4(acc[i][0], acc[i][1], acc[i][2], acc[i][3]);
        *(float4*)(gp+4) = make_float4(acc[i][4], acc[i][5], acc[i][6], acc[i][7]);
    }
}

// ---------------- row softmax, output packed bf16 hi/lo (in-place) ----------------
// Row layout after this kernel (as uints): [0,512) = hi pairs (k2), [512,1024) = lo pairs
__global__ __launch_bounds__(256) void softmax_kernel()
{
    int which = blockIdx.z, t = blockIdx.y;
    float* S = (which ? d_Su : d_Sg) + (size_t)t*NN*NN;
    int warp = threadIdx.x >> 5, lane = threadIdx.x & 31;
    int row = blockIdx.x*8 + warp;
    float4* p = (float4*)(S + (size_t)row*NN);
    float4 v[8];
    float mx = -1e30f;
#pragma unroll
    for (int i = 0; i < 8; i++) {
        v[i] = p[lane + i*32];
        mx = fmaxf(mx, fmaxf(fmaxf(v[i].x, v[i].y), fmaxf(v[i].z, v[i].w)));
    }
#pragma unroll
    for (int o = 16; o > 0; o >>= 1) mx = fmaxf(mx, __shfl_xor_sync(0xffffffffu, mx, o));
    float sum = 0.f;
#pragma unroll
    for (int i = 0; i < 8; i++) {
        v[i].x = __expf(v[i].x - mx); v[i].y = __expf(v[i].y - mx);
        v[i].z = __expf(v[i].z - mx); v[i].w = __expf(v[i].w - mx);
        sum += v[i].x + v[i].y + v[i].z + v[i].w;
    }
#pragma unroll
    for (int o = 16; o > 0; o >>= 1) sum += __shfl_xor_sync(0xffffffffu, sum, o);
    float inv = 1.f / sum;
    unsigned* ur = (unsigned*)(S + (size_t)row*NN);
#pragma unroll
    for (int i = 0; i < 8; i++) {
        float a = v[i].x*inv, b = v[i].y*inv, c = v[i].z*inv, d = v[i].w*inv;
        unsigned h0, l0, h1, l1;
        split_pack(a, b, h0, l0);
        split_pack(c, d, h1, l1);
        int j0 = 2*(lane + i*32);
        ur[j0]       = h0; ur[j0+1]       = h1;
        ur[512 + j0] = l0; ur[512 + j0+1] = l1;
    }
}

// ---------------- pack Xg at t=0: cat[x_0, zeros] ----------------
__global__ void pack0_kernel(const float* __restrict__ x)
{
    int idx = blockIdx.x*blockDim.x + threadIdx.x;
    if (idx >= NN*LCOLS) return;
    int n   = idx / LCOLS;
    int rem = idx - n*LCOLS;
    int b   = rem / CC;
    int c   = rem - b*CC;
    d_Xg[idx] = (c == 0) ? x[(b*TT + 0)*NN + n] : 0.f;
}

// ---------------- bf16x3 tensor-core GEMM: C[1024,4160] = S @ B ----------------
__device__ __forceinline__ const float* gemm_src(int id)
{
    switch (id) {
        case 0: return d_Xg;  case 1: return d_Y1g; case 2: return d_Y2g;
        case 3: return d_Xu;  case 4: return d_Y1u; default: return d_Y2u;
    }
}
__device__ __forceinline__ float* gemm_dst(int id)
{
    switch (id) {
        case 1: return d_Y1g; case 2: return d_Y2g;
        case 4: return d_Y1u; default: return d_Y2u;
    }
}

#define SPAD 136   // uint row stride: conflict-free fragment LDS

__global__ __launch_bounds__(256, 2) void mma_gemm_kernel(int su, int t, int bsel, int csel)
{
    const int K = NN, L = LCOLS;
    // A is pre-packed bf16 hi/lo (softmax output)
    const unsigned* __restrict__ Apk = (const unsigned*)((su ? d_Su : d_Sg) + (size_t)t*NN*NN);
    const float* __restrict__ B = gemm_src(bsel);
    float* __restrict__ C = gemm_dst(csel);

    __shared__ unsigned Ah[2][8][SPAD], Al[2][8][SPAD];
    __shared__ unsigned Bh[2][8][SPAD], Bl[2][8][SPAD];

    int tid  = threadIdx.x;
    int warp = tid >> 5, lane = tid & 31;
    int wm = (warp >> 2) * 64;
    int wn = (warp & 3) * 32;
    int grp = lane >> 2, tig = lane & 3;

    int aRow = tid >> 2;              // 0..63 (+64 second rep)
    int aK2  = (tid & 3) << 1;        // pair index 0,2,4,6
    int bCol = (tid & 31) << 2;
    int bRow2 = tid >> 5;

    const unsigned* ApH0 = Apk + (size_t)(blockIdx.y*128 + aRow)*1024 + aK2;
    const unsigned* ApH1 = Apk + (size_t)(blockIdx.y*128 + aRow + 64)*1024 + aK2;
    int gcol = blockIdx.x*128 + bCol;
    bool bok = gcol < L;
    const float* Bp0 = B + (size_t)(2*bRow2)*L + gcol;
    const float* Bp1 = B + (size_t)(2*bRow2 + 1)*L + gcol;

    float acc[4][4][4];
#pragma unroll
    for (int i = 0; i < 4; i++)
#pragma unroll
        for (int j = 0; j < 4; j++)
#pragma unroll
            for (int c = 0; c < 4; c++) acc[i][j][c] = 0.f;

    // ---- stage tile 0 ----
    {
        uint2 h0 = *(const uint2*)ApH0;
        uint2 l0 = *(const uint2*)(ApH0 + 512);
        uint2 h1 = *(const uint2*)ApH1;
        uint2 l1 = *(const uint2*)(ApH1 + 512);
        Ah[0][aK2  ][aRow]    = h0.x; Ah[0][aK2+1][aRow]    = h0.y;
        Al[0][aK2  ][aRow]    = l0.x; Al[0][aK2+1][aRow]    = l0.y;
        Ah[0][aK2  ][aRow+64] = h1.x; Ah[0][aK2+1][aRow+64] = h1.y;
        Al[0][aK2  ][aRow+64] = l1.x; Al[0][aK2+1][aRow+64] = l1.y;
        float4 b0 = bok ? *(const float4*)Bp0 : make_float4(0,0,0,0);
        float4 b1 = bok ? *(const float4*)Bp1 : make_float4(0,0,0,0);
        uint4 uh, ul;
        split_pack(b0.x, b1.x, uh.x, ul.x);
        split_pack(b0.y, b1.y, uh.y, ul.y);
        split_pack(b0.z, b1.z, uh.z, ul.z);
        split_pack(b0.w, b1.w, uh.w, ul.w);
        *(uint4*)&Bh[0][bRow2][bCol] = uh;
        *(uint4*)&Bl[0][bRow2][bCol] = ul;
    }
    __syncthreads();

    int buf = 0;
    for (int k0 = 0; k0 < K; k0 += 16) {
        bool pf = (k0 + 16) < K;
        uint2 ph0, pl0, ph1, pl1;
        float4 pb0, pb1;
        if (pf) {
            int k2n = (k0 + 16) >> 1;
            ph0 = *(const uint2*)(ApH0 + k2n);
            pl0 = *(const uint2*)(ApH0 + 512 + k2n);
            ph1 = *(const uint2*)(ApH1 + k2n);
            pl1 = *(const uint2*)(ApH1 + 512 + k2n);
            pb0 = bok ? *(const float4*)(Bp0 + (size_t)(k0 + 16)*L) : make_float4(0,0,0,0);
            pb1 = bok ? *(const float4*)(Bp1 + (size_t)(k0 + 16)*L) : make_float4(0,0,0,0);
        }
        // ---- compute on buf ----
        unsigned bh[4][2], bl[4][2];
#pragma unroll
        for (int nt = 0; nt < 4; nt++) {
            int n = wn + nt*8 + grp;
            bh[nt][0] = Bh[buf][tig  ][n];
            bh[nt][1] = Bh[buf][tig+4][n];
            bl[nt][0] = Bl[buf][tig  ][n];
            bl[nt][1] = Bl[buf][tig+4][n];
        }
#pragma unroll
        for (int mt = 0; mt < 4; mt++) {
            int m = wm + mt*16;
            unsigned ah0 = Ah[buf][tig  ][m+grp];
            unsigned ah1 = Ah[buf][tig  ][m+grp+8];
            unsigned ah2 = Ah[buf][tig+4][m+grp];
            unsigned ah3 = Ah[buf][tig+4][m+grp+8];
            unsigned al0 = Al[buf][tig  ][m+grp];
            unsigned al1 = Al[buf][tig  ][m+grp+8];
            unsigned al2 = Al[buf][tig+4][m+grp];
            unsigned al3 = Al[buf][tig+4][m+grp+8];
#pragma unroll
            for (int nt = 0; nt < 4; nt++) {
                mma_bf16(acc[mt][nt][0], acc[mt][nt][1], acc[mt][nt][2], acc[mt][nt][3],
                         ah0, ah1, ah2, ah3, bh[nt][0], bh[nt][1]);
                mma_bf16(acc[mt][nt][0], acc[mt][nt][1], acc[mt][nt][2], acc[mt][nt][3],
                         ah0, ah1, ah2, ah3, bl[nt][0], bl[nt][1]);
                mma_bf16(acc[mt][nt][0], acc[mt][nt][1], acc[mt][nt][2], acc[mt][nt][3],
                         al0, al1, al2, al3, bh[nt][0], bh[nt][1]);
            }
        }
        if (pf) {
            int nb = buf ^ 1;
            Ah[nb][aK2  ][aRow]    = ph0.x; Ah[nb][aK2+1][aRow]    = ph0.y;
            Al[nb][aK2  ][aRow]    = pl0.x; Al[nb][aK2+1][aRow]    = pl0.y;
            Ah[nb][aK2  ][aRow+64] = ph1.x; Ah[nb][aK2+1][aRow+64] = ph1.y;
            Al[nb][aK2  ][aRow+64] = pl1.x; Al[nb][aK2+1][aRow+64] = pl1.y;
            uint4 uh, ul;
            split_pack(pb0.x, pb1.x, uh.x, ul.x);
            split_pack(pb0.y, pb1.y, uh.y, ul.y);
            split_pack(pb0.z, pb1.z, uh.z, ul.z);
            split_pack(pb0.w, pb1.w, uh.w, ul.w);
            *(uint4*)&Bh[nb][bRow2][bCol] = uh;
            *(uint4*)&Bl[nb][bRow2][bCol] = ul;
            __syncthreads();
            buf = nb;
        }
    }

#pragma unroll
    for (int mt = 0; mt < 4; mt++) {
        int row = blockIdx.y*128 + wm + mt*16 + grp;
#pragma unroll
        for (int nt = 0; nt < 4; nt++) {
            int col = blockIdx.x*128 + wn + nt*8 + tig*2;
            if (col < L) {
                *(float2*)&C[(size_t)row*L + col]     = make_float2(acc[mt][nt][0], acc[mt][nt][1]);
                *(float2*)&C[(size_t)(row+8)*L + col] = make_float2(acc[mt][nt][2], acc[mt][nt][3]);
            }
        }
    }
}

// ================= tensor-core GCN epilogues (2 nodes / block, 512 threads) =================
// SMEM carve (gate): xraw[2][3*4160] fp32 | Wh[2][8][136] | Wl[2][8][136] | bias[2][128] | nes[2][16]
#define GATE_SMEM (2*3*LCOLS*4 + 2*8*136*4*2 + 2*128*4 + 2*16*4)
#define UPD_SMEM  (2*3*LCOLS*4 + 2*8*72*4*2  + 2*64*4  + 2*16*4)

// Build A fragment (hi+lo) for rows b, b+8 at kglob base kg (pairs kg,kg+1 and kg+8,kg+9)
__device__ __forceinline__ float xval(const float* xr, int b, int kg)
{
    if (kg >= 195) return 0.f;
    int s = kg / 65;
    int i = kg - s*65;
    return xr[s*LCOLS + b*CC + i];
}

__global__ __launch_bounds__(512) void gate_epi_mma(
    const float* __restrict__ gW, const float* __restrict__ gb,
    const float* __restrict__ x, int t)
{
    extern __shared__ char smem[];
    float* xraw = (float*)smem;                                  // [2][12480]
    unsigned* WhB = (unsigned*)(smem + 2*3*LCOLS*4);             // [2][8][136]
    unsigned* WlB = WhB + 2*8*136;
    float* sbias  = (float*)(WlB + 2*8*136);                     // [2][128]
    float* nes    = sbias + 2*128;                               // [2][16]

    int tid = threadIdx.x;
    int n0 = blockIdx.x*2;

    // stage x rows for both nodes (supports 0: Xg, 1: Y1g, 2: 2*Y2g - Xg)
    for (int c = tid; c < LCOLS; c += 512) {
#pragma unroll
        for (int nd = 0; nd < 2; nd++) {
            size_t off = (size_t)(n0+nd)*LCOLS + c;
            float xv = d_Xg[off];
            float* xr = xraw + nd*(3*LCOLS);
            xr[c]           = xv;
            xr[LCOLS + c]   = d_Y1g[off];
            xr[2*LCOLS + c] = 2.f*d_Y2g[off] - xv;
        }
    }
    if (tid < 32) {
        int nd = tid >> 4, d = tid & 15;
        nes[nd*16 + d] = d_ne_g[(size_t)(t*NN + n0 + nd)*DD + d];
    }
    __syncthreads();

    // bias[node][o] = sum_d ne[d]*gb[d][o]
    if (tid < 256) {
        int nd = tid >> 7, o = tid & 127;
        float s = 0.f;
#pragma unroll
        for (int d = 0; d < DD; d++) s += nes[nd*16 + d]*gb[d*OG + o];
        sbias[nd*128 + o] = s;
    }

    int wid = tid >> 5, lane = tid & 31;
    int nd = wid >> 3, w8 = wid & 7;
    int wm = (w8 >> 2)*32, wn = (w8 & 3)*32;
    int grp = lane >> 2, tig = lane & 3;
    const float* xr = xraw + nd*(3*LCOLS);
    unsigned* Wh = WhB + nd*8*136;
    unsigned* Wl = WlB + nd*8*136;

    float acc[2][4][4];
#pragma unroll
    for (int i = 0; i < 2; i++)
#pragma unroll
        for (int j = 0; j < 4; j++)
#pragma unroll
            for (int c = 0; c < 4; c++) acc[i][j][c] = 0.f;

    for (int ch = 0; ch < 13; ch++) {
        // ---- generate Wn chunk (both nodes share gW loads) ----
#pragma unroll
        for (int rep = 0; rep < 2; rep++) {
            int slot = tid + rep*512;          // 1024 slots: (r2, o)
            int r2 = slot >> 7, o = slot & 127;
            int kg0 = ch*16 + 2*r2, kg1 = kg0 + 1;
            float w0a = 0.f, w1a = 0.f, w0b = 0.f, w1b = 0.f;
            if (kg0 < 195) {
                int s = kg0/65, i = kg0 - s*65;
                const float* gp = gW + (size_t)(s*CC + i)*OG + o;
#pragma unroll
                for (int d = 0; d < DD; d++) {
                    float gv = gp[(size_t)d*(3*CC*OG)];
                    w0a += nes[d]*gv; w1a += nes[16+d]*gv;
                }
            }
            if (kg1 < 195) {
                int s = kg1/65, i = kg1 - s*65;
                const float* gp = gW + (size_t)(s*CC + i)*OG + o;
#pragma unroll
                for (int d = 0; d < DD; d++) {
                    float gv = gp[(size_t)d*(3*CC*OG)];
                    w0b += nes[d]*gv; w1b += nes[16+d]*gv;
                }
            }
            unsigned h, l;
            split_pack(w0a, w0b, h, l);
            WhB[r2*136 + o] = h; WlB[r2*136 + o] = l;
            split_pack(w1a, w1b, h, l);
            WhB[8*136 + r2*136 + o] = h; WlB[8*136 + r2*136 + o] = l;
        }
        __syncthreads();

        // ---- MMA on chunk ----
        unsigned bh[4][2], bl[4][2];
#pragma unroll
        for (int nt = 0; nt < 4; nt++) {
            int o = wn + nt*8 + grp;
            bh[nt][0] = Wh[tig*136 + o];     bh[nt][1] = Wh[(tig+4)*136 + o];
            bl[nt][0] = Wl[tig*136 + o];     bl[nt][1] = Wl[(tig+4)*136 + o];
        }
        int kgA = ch*16 + 2*tig;
#pragma unroll
        for (int mt = 0; mt < 2; mt++) {
            int b0 = wm + mt*16 + grp, b1 = b0 + 8;
            unsigned ah0, al0, ah1, al1, ah2, al2, ah3, al3;
            split_pack(xval(xr,b0,kgA),   xval(xr,b0,kgA+1), ah0, al0);
            split_pack(xval(xr,b1,kgA),   xval(xr,b1,kgA+1), ah1, al1);
            split_pack(xval(xr,b0,kgA+8), xval(xr,b0,kgA+9), ah2, al2);
            split_pack(xval(xr,b1,kgA+8), xval(xr,b1,kgA+9), ah3, al3);
#pragma unroll
            for (int nt = 0; nt < 4; nt++) {
                mma_bf16(acc[mt][nt][0], acc[mt][nt][1], acc[mt][nt][2], acc[mt][nt][3],
                         ah0, ah1, ah2, ah3, bh[nt][0], bh[nt][1]);
                mma_bf16(acc[mt][nt][0], acc[mt][nt][1], acc[mt][nt][2], acc[mt][nt][3],
                         ah0, ah1, ah2, ah3, bl[nt][0], bl[nt][1]);
                mma_bf16(acc[mt][nt][0], acc[mt][nt][1], acc[mt][nt][2], acc[mt][nt][3],
                         al0, al1, al2, al3, bh[nt][0], bh[nt][1]);
            }
        }
        __syncthreads();
    }

    // ---- finalize: sigmoid; z (o<64) -> Xu = z*h ; r (o>=64) -> d_r ----
    int n = n0 + nd;
#pragma unroll
    for (int mt = 0; mt < 2; mt++) {
#pragma unroll
        for (int nt = 0; nt < 4; nt++) {
            int o0 = wn + nt*8 + tig*2;
#pragma unroll
            for (int c = 0; c < 4; c++) {
                int b = wm + mt*16 + grp + ((c >> 1) ? 8 : 0);
                int o = o0 + (c & 1);
                float v = 1.f/(1.f + __expf(-(acc[mt][nt][c] + sbias[nd*128 + o])));
                if (o < HH) {
                    float hv = d_h[(size_t)(n*BB + b)*HH + o];
                    d_Xu[(size_t)n*LCOLS + b*CC + 1 + o] = v*hv;
                    if (o == 0)
                        d_Xu[(size_t)n*LCOLS + b*CC] = x[(size_t)(b*TT + t)*NN + n];
                } else {
                    d_r[(size_t)(n*BB + b)*HH + (o - HH)] = v;
                }
            }
        }
    }
}

__global__ __launch_bounds__(512) void update_epi_mma(
    const float* __restrict__ uW, const float* __restrict__ ub,
    float* __restrict__ out, const float* __restrict__ x, int t)
{
    extern __shared__ char smem[];
    float* xraw = (float*)smem;                                  // [2][12480]
    unsigned* WhB = (unsigned*)(smem + 2*3*LCOLS*4);             // [2][8][72]
    unsigned* WlB = WhB + 2*8*72;
    float* sbias  = (float*)(WlB + 2*8*72);                      // [2][64]
    float* nes    = sbias + 2*64;                                // [2][16]

    int tid = threadIdx.x;
    int n0 = blockIdx.x*2;

    for (int c = tid; c < LCOLS; c += 512) {
#pragma unroll
        for (int nd = 0; nd < 2; nd++) {
            size_t off = (size_t)(n0+nd)*LCOLS + c;
            float xv = d_Xu[off];
            float* xr = xraw + nd*(3*LCOLS);
            xr[c]           = xv;
            xr[LCOLS + c]   = d_Y1u[off];
            xr[2*LCOLS + c] = 2.f*d_Y2u[off] - xv;
        }
    }
    if (tid < 32) {
        int nd = tid >> 4, d = tid & 15;
        nes[nd*16 + d] = d_ne_u[(size_t)(t*NN + n0 + nd)*DD + d];
    }
    __syncthreads();

    if (tid < 128) {
        int nd = tid >> 6, o = tid & 63;
        float s = 0.f;
#pragma unroll
        for (int d = 0; d < DD; d++) s += nes[nd*16 + d]*ub[d*OU + o];
        sbias[nd*64 + o] = s;
    }

    int wid = tid >> 5, lane = tid & 31;
    int nd = wid >> 3, w8 = wid & 7;
    int wm = (w8 >> 2)*32, wn = (w8 & 3)*16;   // N=64: warp covers 16 cols = 2 n8 tiles
    int grp = lane >> 2, tig = lane & 3;
    const float* xr = xraw + nd*(3*LCOLS);
    unsigned* Wh = WhB + nd*8*72;
    unsigned* Wl = WlB + nd*8*72;

    float acc[2][2][4];
#pragma unroll
    for (int i = 0; i < 2; i++)
#pragma unroll
        for (int j = 0; j < 2; j++)
#pragma unroll
            for (int c = 0; c < 4; c++) acc[i][j][c] = 0.f;

    for (int ch = 0; ch < 13; ch++) {
        {
            int slot = tid;                 // 512 slots: (r2, o), o<64
            int r2 = slot >> 6, o = slot & 63;
            int kg0 = ch*16 + 2*r2, kg1 = kg0 + 1;
            float w0a = 0.f, w1a = 0.f, w0b = 0.f, w1b = 0.f;
            if (kg0 < 195) {
                int s = kg0/65, i = kg0 - s*65;
                const float* gp = uW + (size_t)(s*CC + i)*OU + o;
#pragma unroll
                for (int d = 0; d < DD; d++) {
                    float gv = gp[(size_t)d*(3*CC*OU)];
                    w0a += nes[d]*gv; w1a += nes[16+d]*gv;
                }
            }
            if (kg1 < 195) {
                int s = kg1/65, i = kg1 - s*65;
                const float* gp = uW + (size_t)(s*CC + i)*OU + o;
#pragma unroll
                for (int d = 0; d < DD; d++) {
                    float gv = gp[(size_t)d*(3*CC*OU)];
                    w0b += nes[d]*gv; w1b += nes[16+d]*gv;
                }
            }
            unsigned h, l;
            split_pack(w0a, w0b, h, l);
            WhB[r2*72 + o] = h; WlB[r2*72 + o] = l;
            split_pack(w1a, w1b, h, l);
            WhB[8*72 + r2*72 + o] = h; WlB[8*72 + r2*72 + o] = l;
        }
        __syncthreads();

        unsigned bh[2][2], bl[2][2];
#pragma unroll
        for (int nt = 0; nt < 2; nt++) {
            int o = wn + nt*8 + grp;
            bh[nt][0] = Wh[tig*72 + o];     bh[nt][1] = Wh[(tig+4)*72 + o];
            bl[nt][0] = Wl[tig*72 + o];     bl[nt][1] = Wl[(tig+4)*72 + o];
        }
        int kgA = ch*16 + 2*tig;
#pragma unroll
        for (int mt = 0; mt < 2; mt++) {
            int b0 = wm + mt*16 + grp, b1 = b0 + 8;
            unsigned ah0, al0, ah1, al1, ah2, al2, ah3, al3;
            split_pack(xval(xr,b0,kgA),   xval(xr,b0,kgA+1), ah0, al0);
            split_pack(xval(xr,b1,kgA),   xval(xr,b1,kgA+1), ah1, al1);
            split_pack(xval(xr,b0,kgA+8), xval(xr,b0,kgA+9), ah2, al2);
            split_pack(xval(xr,b1,kgA+8), xval(xr,b1,kgA+9), ah3, al3);
#pragma unroll
            for (int nt = 0; nt < 2; nt++) {
                mma_bf16(acc[mt][nt][0], acc[mt][nt][1], acc[mt][nt][2], acc[mt][nt][3],
                         ah0, ah1, ah2, ah3, bh[nt][0], bh[nt][1]);
                mma_bf16(acc[mt][nt][0], acc[mt][nt][1], acc[mt][nt][2], acc[mt][nt][3],
                         ah0, ah1, ah2, ah3, bl[nt][0], bl[nt][1]);
                mma_bf16(acc[mt][nt][0], acc[mt][nt][1], acc[mt][nt][2], acc[mt][nt][3],
                         al0, al1, al2, al3, bh[nt][0], bh[nt][1]);
            }
        }
        __syncthreads();
    }

    // ---- finalize: tanh + GRU combine; write h, out, and next Xg ----
    int n = n0 + nd;
#pragma unroll
    for (int mt = 0; mt < 2; mt++) {
#pragma unroll
        for (int nt = 0; nt < 2; nt++) {
            int o0 = wn + nt*8 + tig*2;
#pragma unroll
            for (int c = 0; c < 4; c++) {
                int b = wm + mt*16 + grp + ((c >> 1) ? 8 : 0);
                int o = o0 + (c & 1);
                float hc = tanhf(acc[mt][nt][c] + sbias[nd*64 + o]);
                size_t idx = (size_t)(n*BB + b)*HH + o;
                float hv = d_h[idx];
                float rv = d_r[idx];
                float hn = rv*hv + (1.f - rv)*hc;
                d_h[idx] = hn;
                out[((size_t)(b*TT + t)*NN + n)*HH + o] = hn;
                if (t + 1 < TT) {
                    d_Xg[(size_t)n*LCOLS + b*CC + 1 + o] = hn;
                    if (o == 0)
                        d_Xg[(size_t)n*LCOLS + b*CC] = x[(size_t)(b*TT + t+1)*NN + n];
                }
            }
        }
    }
}

// ---------------- host launcher ----------------
extern "C" void kernel_launch(void* const* d_in, const int* in_sizes, int n_in,
                              void* d_out, int out_size)
{
    const float *x = nullptr, *nodeE = nullptr, *timeE = nullptr;
    const float *gW = nullptr, *gb = nullptr, *uW = nullptr, *ub = nullptr;
    const float *ln16[4] = {nullptr, nullptr, nullptr, nullptr};
    int nln = 0;
    for (int i = 0; i < n_in; i++) {
        const float* p = (const float*)d_in[i];
        switch (in_sizes[i]) {
            case 786432: x = p; break;      // [64,12,1024,1]
            case 16384:  nodeE = p; break;  // [1024,16]
            case 192:    timeE = p; break;  // [12,16]
            case 399360: gW = p; break;     // [16,3,65,128]
            case 2048:   gb = p; break;     // [16,128]
            case 199680: uW = p; break;     // [16,3,65,64]
            case 1024:   ub = p; break;     // [16,64]
            case 16:     if (nln < 4) ln16[nln++] = p; break;
            default: break;
        }
    }
    const float* glg = ln16[0]; const float* glb = ln16[1];
    const float* ulg = ln16[2]; const float* ulb = ln16[3];
    float* out = (float*)d_out;

    cudaFuncSetAttribute(gate_epi_mma,  cudaFuncAttributeMaxDynamicSharedMemorySize, GATE_SMEM);
    cudaFuncSetAttribute(update_epi_mma, cudaFuncAttributeMaxDynamicSharedMemorySize, UPD_SMEM);

    zero_h_kernel<<<(NN*BB*HH + 255)/256, 256>>>();
    compute_ne_kernel<<<(TT*NN + 255)/256, 256>>>(nodeE, timeE, glg, glb, ulg, ulb);
    score_kernel<<<dim3(8, 8, 2*TT), 256>>>();
    softmax_kernel<<<dim3(128, TT, 2), 256>>>();
    pack0_kernel<<<((size_t)NN*LCOLS + 255)/256, 256>>>(x);

    dim3 ggrid((LCOLS + 127)/128, NN/128);   // (33, 8)
    for (int t = 0; t < TT; t++) {
        mma_gemm_kernel<<<ggrid, 256>>>(0, t, 0, 1);   // Y1g = Sg @ Xg
        mma_gemm_kernel<<<ggrid, 256>>>(0, t, 1, 2);   // Y2g = Sg @ Y1g
        gate_epi_mma<<<NN/2, 512, GATE_SMEM>>>(gW, gb, x, t);
        mma_gemm_kernel<<<ggrid, 256>>>(1, t, 3, 4);   // Y1u = Su @ Xu
        mma_gemm_kernel<<<ggrid, 256>>>(1, t, 4, 5);   // Y2u = Su @ Y1u
        update_epi_mma<<<NN/2, 512, UPD_SMEM>>>(uW, ub, out, x, t);
    }
}

// round 6
// speedup vs baseline: 1.9892x; 1.0264x over previous
#include <cuda_runtime.h>
#include <cuda_bf16.h>
#include <math.h>

// Problem constants
#define NN 1024   // nodes
#define BB 64     // batch
#define TT 12     // time steps
#define DD 16     // embedding dim
#define HH 64     // hidden
#define CC 65     // C_IN + H
#define LCOLS (BB*CC)   // 4160
#define OG 128    // gate output (2H)
#define OU 64     // update output (H)
#define NP2 512   // node pairs (NN/2)

// ---------------- scratch (static device allocations) ----------------
__device__ float d_ne_g[TT*NN*DD];
__device__ float d_ne_u[TT*NN*DD];
__device__ float d_Sg[(size_t)TT*NN*NN];   // scores -> packed bf16 hi/lo after softmax
__device__ float d_Su[(size_t)TT*NN*NN];
__device__ float d_h [NN*BB*HH];           // [N,B,H] fp32
__device__ float d_r [NN*BB*HH];           // fp32
// The following hold PACKED bf16 hi/lo planes: [0,512*LCOLS) = hi uints [k2][col],
// [512*LCOLS, 1024*LCOLS) = lo uints. (Same byte size as the old fp32 layout.)
__device__ float d_Xg [(size_t)NN*LCOLS];
__device__ float d_Y1g[(size_t)NN*LCOLS];
__device__ float d_Y2g[(size_t)NN*LCOLS];
__device__ float d_Xu [(size_t)NN*LCOLS];
__device__ float d_Y1u[(size_t)NN*LCOLS];
__device__ float d_Y2u[(size_t)NN*LCOLS];

// ---------------- helpers ----------------
__device__ __forceinline__ unsigned pack_bf16(float v0, float v1)  // low half = v0
{
    __nv_bfloat162 t = __floats2bfloat162_rn(v0, v1);
    return *(unsigned*)&t;
}
__device__ __forceinline__ void split_pack(float v0, float v1, unsigned& hi, unsigned& lo)
{
    __nv_bfloat16 h0 = __float2bfloat16(v0);
    __nv_bfloat16 h1 = __float2bfloat16(v1);
    float r0 = v0 - __bfloat162float(h0);
    float r1 = v1 - __bfloat162float(h1);
    hi = ((unsigned)__bfloat16_as_ushort(h1) << 16) | (unsigned)__bfloat16_as_ushort(h0);
    lo = pack_bf16(r0, r1);
}
__device__ __forceinline__ void unpack2(unsigned h, unsigned l, float& a, float& b)
{
    __nv_bfloat162 hh = *reinterpret_cast<__nv_bfloat162*>(&h);
    __nv_bfloat162 ll = *reinterpret_cast<__nv_bfloat162*>(&l);
    a = __bfloat162float(hh.x) + __bfloat162float(ll.x);
    b = __bfloat162float(hh.y) + __bfloat162float(ll.y);
}
__device__ __forceinline__ void mma_bf16(float& c0, float& c1, float& c2, float& c3,
    unsigned a0, unsigned a1, unsigned a2, unsigned a3, unsigned b0, unsigned b1)
{
    asm volatile("mma.sync.aligned.m16n8k16.row.col.f32.bf16.bf16.f32 "
        "{%0,%1,%2,%3}, {%4,%5,%6,%7}, {%8,%9}, {%0,%1,%2,%3};\n"
        : "+f"(c0), "+f"(c1), "+f"(c2), "+f"(c3)
        : "r"(a0), "r"(a1), "r"(a2), "r"(a3), "r"(b0), "r"(b1));
}

// ---------------- h = 0 ----------------
__global__ void zero_h_kernel()
{
    int i = blockIdx.x*blockDim.x + threadIdx.x;
    if (i < NN*BB*HH) d_h[i] = 0.f;
}

// ---------------- layernormed node+time embeddings, all t ----------------
__global__ void compute_ne_kernel(const float* __restrict__ nodeE,
                                  const float* __restrict__ timeE,
                                  const float* __restrict__ gg, const float* __restrict__ gbeta,
                                  const float* __restrict__ ug, const float* __restrict__ ubeta)
{
    int idx = blockIdx.x*blockDim.x + threadIdx.x;   // t*NN + n
    if (idx >= TT*NN) return;
    int t = idx >> 10;
    int n = idx & (NN-1);
    float v[DD];
    float mu = 0.f;
#pragma unroll
    for (int d = 0; d < DD; d++) { v[d] = nodeE[n*DD+d] + timeE[t*DD+d]; mu += v[d]; }
    mu *= (1.f/DD);
    float var = 0.f;
#pragma unroll
    for (int d = 0; d < DD; d++) { float dv = v[d]-mu; var += dv*dv; }
    var *= (1.f/DD);
    float inv = 1.f / sqrtf(var + 1e-12f);
#pragma unroll
    for (int d = 0; d < DD; d++) {
        float nv = (v[d]-mu)*inv;
        d_ne_g[idx*DD+d] = nv*gg[d] + gbeta[d];
        d_ne_u[idx*DD+d] = nv*ug[d] + ubeta[d];
    }
}

// ---------------- scores G = ne @ ne^T  (fp32, into d_Sg/d_Su) ----------------
__global__ __launch_bounds__(256) void score_kernel()
{
    int z = blockIdx.z;
    int which = (z >= TT) ? 1 : 0;
    int t = which ? (z - TT) : z;
    const float* __restrict__ ne = (which ? d_ne_u : d_ne_g) + t*NN*DD;
    float* __restrict__ G = (which ? d_Su : d_Sg) + (size_t)t*NN*NN;
    __shared__ float Rt[DD][132];
    __shared__ float Ct[DD][132];
    int tid = threadIdx.x;
#pragma unroll
    for (int rep = 0; rep < 2; rep++) {
        int f = tid + rep*256;
        int r = f >> 2, q = (f & 3) << 2;
        float4 v = *(const float4*)(ne + (blockIdx.y*128 + r)*DD + q);
        Rt[q+0][r] = v.x; Rt[q+1][r] = v.y; Rt[q+2][r] = v.z; Rt[q+3][r] = v.w;
        float4 w = *(const float4*)(ne + (blockIdx.x*128 + r)*DD + q);
        Ct[q+0][r] = w.x; Ct[q+1][r] = w.y; Ct[q+2][r] = w.z; Ct[q+3][r] = w.w;
    }
    __syncthreads();
    int ty = tid >> 4, tx = tid & 15;
    int r0 = ty*8, c0 = tx*8;
    float acc[8][8];
#pragma unroll
    for (int i = 0; i < 8; i++)
#pragma unroll
        for (int j = 0; j < 8; j++) acc[i][j] = 0.f;
#pragma unroll
    for (int k = 0; k < DD; k++) {
        float rv[8], cv[8];
        *(float4*)&rv[0] = *(const float4*)&Rt[k][r0];
        *(float4*)&rv[4] = *(const float4*)&Rt[k][r0+4];
        *(float4*)&cv[0] = *(const float4*)&Ct[k][c0];
        *(float4*)&cv[4] = *(const float4*)&Ct[k][c0+4];
#pragma unroll
        for (int i = 0; i < 8; i++)
#pragma unroll
            for (int j = 0; j < 8; j++) acc[i][j] += rv[i]*cv[j];
    }
#pragma unroll
    for (int i = 0; i < 8; i++) {
        float* gp = G + (size_t)(blockIdx.y*128 + r0 + i)*NN + blockIdx.x*128 + c0;
        *(float4*)gp     = make_float4(acc[i][0], acc[i][1], acc[i][2], acc[i][3]);
        *(float4*)(gp+4) = make_float4(acc[i][4], acc[i][5], acc[i][6], acc[i][7]);
    }
}

// ---------------- row softmax, output packed bf16 hi/lo (in-place) ----------------
// Row layout after (uints): [0,512) hi pairs (k2), [512,1024) lo pairs
__global__ __launch_bounds__(256) void softmax_kernel()
{
    int which = blockIdx.z, t = blockIdx.y;
    float* S = (which ? d_Su : d_Sg) + (size_t)t*NN*NN;
    int warp = threadIdx.x >> 5, lane = threadIdx.x & 31;
    int row = blockIdx.x*8 + warp;
    float4* p = (float4*)(S + (size_t)row*NN);
    float4 v[8];
    float mx = -1e30f;
#pragma unroll
    for (int i = 0; i < 8; i++) {
        v[i] = p[lane + i*32];
        mx = fmaxf(mx, fmaxf(fmaxf(v[i].x, v[i].y), fmaxf(v[i].z, v[i].w)));
    }
#pragma unroll
    for (int o = 16; o > 0; o >>= 1) mx = fmaxf(mx, __shfl_xor_sync(0xffffffffu, mx, o));
    float sum = 0.f;
#pragma unroll
    for (int i = 0; i < 8; i++) {
        v[i].x = __expf(v[i].x - mx); v[i].y = __expf(v[i].y - mx);
        v[i].z = __expf(v[i].z - mx); v[i].w = __expf(v[i].w - mx);
        sum += v[i].x + v[i].y + v[i].z + v[i].w;
    }
#pragma unroll
    for (int o = 16; o > 0; o >>= 1) sum += __shfl_xor_sync(0xffffffffu, sum, o);
    float inv = 1.f / sum;
    unsigned* ur = (unsigned*)(S + (size_t)row*NN);
#pragma unroll
    for (int i = 0; i < 8; i++) {
        float a = v[i].x*inv, b = v[i].y*inv, c = v[i].z*inv, d = v[i].w*inv;
        unsigned h0, l0, h1, l1;
        split_pack(a, b, h0, l0);
        split_pack(c, d, h1, l1);
        int j0 = 2*(lane + i*32);
        ur[j0]       = h0; ur[j0+1]       = h1;
        ur[512 + j0] = l0; ur[512 + j0+1] = l1;
    }
}

// ---------------- pack Xg at t=0 (packed planes) ----------------
__global__ void pack0_kernel(const float* __restrict__ x)
{
    int idx = blockIdx.x*blockDim.x + threadIdx.x;
    if (idx >= NP2*LCOLS) return;
    int i = idx / LCOLS;
    int c = idx - i*LCOLS;
    int b = c / CC, cc = c - b*CC;
    unsigned h = 0, l = 0;
    if (cc == 0)
        split_pack(x[(size_t)(b*TT)*NN + 2*i], x[(size_t)(b*TT)*NN + 2*i + 1], h, l);
    unsigned* Xh = (unsigned*)d_Xg;
    Xh[idx] = h;
    Xh[(size_t)NP2*LCOLS + idx] = l;
}

// ---------------- bf16x3 GEMM: C = S @ B  (all operands packed bf16 hi/lo) ----------------
__device__ __forceinline__ const float* gemm_src(int id)
{
    switch (id) {
        case 0: return d_Xg;  case 1: return d_Y1g; case 2: return d_Y2g;
        case 3: return d_Xu;  case 4: return d_Y1u; default: return d_Y2u;
    }
}
__device__ __forceinline__ float* gemm_dst(int id)
{
    switch (id) {
        case 1: return d_Y1g; case 2: return d_Y2g;
        case 4: return d_Y1u; default: return d_Y2u;
    }
}

#define APAD 136   // uint row stride (mod 32 == 8 -> conflict-free frag LDS)
#define BPAD 264
#define GEMM_SMEM ((2*8*APAD*2 + 2*8*BPAD*2)*4)   // 51200 bytes

__global__ __launch_bounds__(256) void mma_gemm2(int su, int t, int bsel, int csel)
{
    extern __shared__ unsigned sm[];
    unsigned* AhS = sm;                      // [2][8][APAD]
    unsigned* AlS = AhS + 2*8*APAD;
    unsigned* BhS = AlS + 2*8*APAD;          // [2][8][BPAD]
    unsigned* BlS = BhS + 2*8*BPAD;

    const unsigned* Apk = (const unsigned*)((su ? d_Su : d_Sg) + (size_t)t*NN*NN);
    const unsigned* Bgh = (const unsigned*)gemm_src(bsel);
    const unsigned* Bgl = Bgh + (size_t)NP2*LCOLS;
    unsigned* Cgh = (unsigned*)gemm_dst(csel);
    unsigned* Cgl = Cgh + (size_t)NP2*LCOLS;

    int tid = threadIdx.x, warp = tid >> 5, lane = tid & 31;
    int wm = (warp >> 2)*64, wn = (warp & 3)*64;   // warp grid 2x4 over 128x256
    int grp = lane >> 2, tig = lane & 3;

    int aRow = tid & 127, aHalf = tid >> 7;
    const unsigned* ApH = Apk + (size_t)(blockIdx.y*128 + aRow)*1024 + aHalf*4;

    int bK2 = tid >> 5, bC4 = tid & 31;
    int colr0 = blockIdx.x*256 + bC4*4;
    int colr1 = colr0 + 128;
    bool ok0 = colr0 < LCOLS, ok1 = colr1 < LCOLS;

    float acc[4][8][4];
#pragma unroll
    for (int i = 0; i < 4; i++)
#pragma unroll
        for (int j = 0; j < 8; j++)
#pragma unroll
            for (int c = 0; c < 4; c++) acc[i][j][c] = 0.f;

    const uint4 z4 = make_uint4(0,0,0,0);
    // ---- prologue: stage k0 = 0 into buf 0 ----
    {
        uint4 h = *(const uint4*)ApH;
        uint4 l = *(const uint4*)(ApH + 512);
        int ab = aHalf*4*APAD;
        AhS[ab + 0*APAD + aRow] = h.x; AhS[ab + 1*APAD + aRow] = h.y;
        AhS[ab + 2*APAD + aRow] = h.z; AhS[ab + 3*APAD + aRow] = h.w;
        AlS[ab + 0*APAD + aRow] = l.x; AlS[ab + 1*APAD + aRow] = l.y;
        AlS[ab + 2*APAD + aRow] = l.z; AlS[ab + 3*APAD + aRow] = l.w;
        size_t brow = (size_t)bK2*LCOLS;
        uint4 b0h = ok0 ? *(const uint4*)(Bgh + brow + colr0) : z4;
        uint4 b1h = ok1 ? *(const uint4*)(Bgh + brow + colr1) : z4;
        uint4 b0l = ok0 ? *(const uint4*)(Bgl + brow + colr0) : z4;
        uint4 b1l = ok1 ? *(const uint4*)(Bgl + brow + colr1) : z4;
        int bb = bK2*BPAD;
        *(uint4*)&BhS[bb + bC4*4]       = b0h;
        *(uint4*)&BhS[bb + 128 + bC4*4] = b1h;
        *(uint4*)&BlS[bb + bC4*4]       = b0l;
        *(uint4*)&BlS[bb + 128 + bC4*4] = b1l;
    }
    __syncthreads();

    int buf = 0;
    for (int k0 = 0; k0 < 1024; k0 += 16) {
        bool pf = (k0 + 16) < 1024;
        uint4 ph, pl, pb0h, pb1h, pb0l, pb1l;
        if (pf) {
            int k2g = (k0 + 16) >> 1;
            ph = *(const uint4*)(ApH + k2g);
            pl = *(const uint4*)(ApH + 512 + k2g);
            size_t brow = (size_t)(k2g + bK2)*LCOLS;
            pb0h = ok0 ? *(const uint4*)(Bgh + brow + colr0) : z4;
            pb1h = ok1 ? *(const uint4*)(Bgh + brow + colr1) : z4;
            pb0l = ok0 ? *(const uint4*)(Bgl + brow + colr0) : z4;
            pb1l = ok1 ? *(const uint4*)(Bgl + brow + colr1) : z4;
        }
        const unsigned* AhB = AhS + buf*8*APAD;
        const unsigned* AlB = AlS + buf*8*APAD;
        const unsigned* BhB = BhS + buf*8*BPAD;
        const unsigned* BlB = BlS + buf*8*BPAD;

        unsigned bh[8][2], bl[8][2];
#pragma unroll
        for (int nt = 0; nt < 8; nt++) {
            int o = wn + nt*8 + grp;
            bh[nt][0] = BhB[tig*BPAD + o];     bh[nt][1] = BhB[(tig+4)*BPAD + o];
            bl[nt][0] = BlB[tig*BPAD + o];     bl[nt][1] = BlB[(tig+4)*BPAD + o];
        }
#pragma unroll
        for (int mt = 0; mt < 4; mt++) {
            int m = wm + mt*16;
            unsigned ah0 = AhB[tig*APAD + m+grp];
            unsigned ah1 = AhB[tig*APAD + m+grp+8];
            unsigned ah2 = AhB[(tig+4)*APAD + m+grp];
            unsigned ah3 = AhB[(tig+4)*APAD + m+grp+8];
            unsigned al0 = AlB[tig*APAD + m+grp];
            unsigned al1 = AlB[tig*APAD + m+grp+8];
            unsigned al2 = AlB[(tig+4)*APAD + m+grp];
            unsigned al3 = AlB[(tig+4)*APAD + m+grp+8];
#pragma unroll
            for (int nt = 0; nt < 8; nt++) {
                mma_bf16(acc[mt][nt][0], acc[mt][nt][1], acc[mt][nt][2], acc[mt][nt][3],
                         ah0, ah1, ah2, ah3, bh[nt][0], bh[nt][1]);
                mma_bf16(acc[mt][nt][0], acc[mt][nt][1], acc[mt][nt][2], acc[mt][nt][3],
                         ah0, ah1, ah2, ah3, bl[nt][0], bl[nt][1]);
                mma_bf16(acc[mt][nt][0], acc[mt][nt][1], acc[mt][nt][2], acc[mt][nt][3],
                         al0, al1, al2, al3, bh[nt][0], bh[nt][1]);
            }
        }
        if (pf) {
            int nb = buf ^ 1;
            int ab = nb*8*APAD + aHalf*4*APAD;
            AhS[ab + 0*APAD + aRow] = ph.x; AhS[ab + 1*APAD + aRow] = ph.y;
            AhS[ab + 2*APAD + aRow] = ph.z; AhS[ab + 3*APAD + aRow] = ph.w;
            AlS[ab + 0*APAD + aRow] = pl.x; AlS[ab + 1*APAD + aRow] = pl.y;
            AlS[ab + 2*APAD + aRow] = pl.z; AlS[ab + 3*APAD + aRow] = pl.w;
            int bb = nb*8*BPAD + bK2*BPAD;
            *(uint4*)&BhS[bb + bC4*4]       = pb0h;
            *(uint4*)&BhS[bb + 128 + bC4*4] = pb1h;
            *(uint4*)&BlS[bb + bC4*4]       = pb0l;
            *(uint4*)&BlS[bb + 128 + bC4*4] = pb1l;
            __syncthreads();
            buf = nb;
        }
    }

    // ---- epilogue: pack row pairs via shfl, write hi/lo planes ----
#pragma unroll
    for (int mt = 0; mt < 4; mt++) {
        int rowbase = blockIdx.y*128 + wm + mt*16;
#pragma unroll
        for (int nt = 0; nt < 8; nt++) {
            float c0 = acc[mt][nt][0], c1 = acc[mt][nt][1];
            float c2 = acc[mt][nt][2], c3 = acc[mt][nt][3];
            float p0 = __shfl_xor_sync(0xffffffffu, c0, 4);
            float p1 = __shfl_xor_sync(0xffffffffu, c1, 4);
            float p2 = __shfl_xor_sync(0xffffffffu, c2, 4);
            float p3 = __shfl_xor_sync(0xffffffffu, c3, 4);
            unsigned h0, l0, h1, l1;
            int k2;
            if (!(grp & 1)) {
                split_pack(c0, p0, h0, l0);   // rows (r, r+1), col0
                split_pack(c1, p1, h1, l1);   // rows (r, r+1), col0+1
                k2 = (rowbase + grp) >> 1;
            } else {
                split_pack(p2, c2, h0, l0);   // rows (r+7, r+8)
                split_pack(p3, c3, h1, l1);
                k2 = (rowbase + 7 + grp) >> 1;
            }
            int col0 = blockIdx.x*256 + wn + nt*8 + tig*2;
            if (col0 < LCOLS) {
                *(uint2*)&Cgh[(size_t)k2*LCOLS + col0] = make_uint2(h0, h1);
                *(uint2*)&Cgl[(size_t)k2*LCOLS + col0] = make_uint2(l0, l1);
            }
        }
    }
}

// ================= tensor-core GCN epilogues (2 nodes / block, 512 threads) =================
#define GATE_SMEM (2*3*LCOLS*4 + 2*8*136*4*2 + 2*128*4 + 2*16*4)
#define UPD_SMEM  (2*3*LCOLS*4 + 2*8*72*4*2  + 2*64*4  + 2*16*4)

__device__ __forceinline__ float xval(const float* xr, int b, int kg)
{
    if (kg >= 195) return 0.f;
    int s = kg / 65;
    int i = kg - s*65;
    return xr[s*LCOLS + b*CC + i];
}

__global__ __launch_bounds__(512) void gate_epi_mma(
    const float* __restrict__ gW, const float* __restrict__ gb,
    const float* __restrict__ x, int t)
{
    extern __shared__ char smem[];
    float* xraw = (float*)smem;                                  // [2][3*LCOLS]
    unsigned* WhB = (unsigned*)(smem + 2*3*LCOLS*4);             // [2][8][136]
    unsigned* WlB = WhB + 2*8*136;
    float* sbias  = (float*)(WlB + 2*8*136);                     // [2][128]
    float* nes    = sbias + 2*128;                               // [2][16]

    int tid = threadIdx.x;
    int ip = blockIdx.x;        // node pair index
    int n0 = ip*2;

    const unsigned* Xh  = (const unsigned*)d_Xg;  const unsigned* Xl  = Xh  + (size_t)NP2*LCOLS;
    const unsigned* Y1h = (const unsigned*)d_Y1g; const unsigned* Y1l = Y1h + (size_t)NP2*LCOLS;
    const unsigned* Y2h = (const unsigned*)d_Y2g; const unsigned* Y2l = Y2h + (size_t)NP2*LCOLS;

    for (int c = tid; c < LCOLS; c += 512) {
        size_t off = (size_t)ip*LCOLS + c;
        float x0, x1, y10, y11, y20, y21;
        unpack2(Xh[off],  Xl[off],  x0,  x1);
        unpack2(Y1h[off], Y1l[off], y10, y11);
        unpack2(Y2h[off], Y2l[off], y20, y21);
        xraw[c]                     = x0;
        xraw[LCOLS + c]             = y10;
        xraw[2*LCOLS + c]           = 2.f*y20 - x0;
        xraw[3*LCOLS + c]           = x1;
        xraw[4*LCOLS + c]           = y11;
        xraw[5*LCOLS + c]           = 2.f*y21 - x1;
    }
    if (tid < 32) {
        int nd = tid >> 4, d = tid & 15;
        nes[nd*16 + d] = d_ne_g[(size_t)(t*NN + n0 + nd)*DD + d];
    }
    __syncthreads();

    if (tid < 256) {
        int nd = tid >> 7, o = tid & 127;
        float s = 0.f;
#pragma unroll
        for (int d = 0; d < DD; d++) s += nes[nd*16 + d]*gb[d*OG + o];
        sbias[nd*128 + o] = s;
    }

    int wid = tid >> 5, lane = tid & 31;
    int nd = wid >> 3, w8 = wid & 7;
    int wm = (w8 >> 2)*32, wn = (w8 & 3)*32;
    int grp = lane >> 2, tig = lane & 3;
    const float* xr = xraw + nd*(3*LCOLS);
    unsigned* Wh = WhB + nd*8*136;
    unsigned* Wl = WlB + nd*8*136;

    float acc[2][4][4];
#pragma unroll
    for (int i = 0; i < 2; i++)
#pragma unroll
        for (int j = 0; j < 4; j++)
#pragma unroll
            for (int c = 0; c < 4; c++) acc[i][j][c] = 0.f;

    for (int ch = 0; ch < 13; ch++) {
#pragma unroll
        for (int rep = 0; rep < 2; rep++) {
            int slot = tid + rep*512;
            int r2 = slot >> 7, o = slot & 127;
            int kg0 = ch*16 + 2*r2, kg1 = kg0 + 1;
            float w0a = 0.f, w1a = 0.f, w0b = 0.f, w1b = 0.f;
            if (kg0 < 195) {
                int s = kg0/65, i = kg0 - s*65;
                const float* gp = gW + (size_t)(s*CC + i)*OG + o;
#pragma unroll
                for (int d = 0; d < DD; d++) {
                    float gv = gp[(size_t)d*(3*CC*OG)];
                    w0a += nes[d]*gv; w1a += nes[16+d]*gv;
                }
            }
            if (kg1 < 195) {
                int s = kg1/65, i = kg1 - s*65;
                const float* gp = gW + (size_t)(s*CC + i)*OG + o;
#pragma unroll
                for (int d = 0; d < DD; d++) {
                    float gv = gp[(size_t)d*(3*CC*OG)];
                    w0b += nes[d]*gv; w1b += nes[16+d]*gv;
                }
            }
            unsigned h, l;
            split_pack(w0a, w0b, h, l);
            WhB[r2*136 + o] = h; WlB[r2*136 + o] = l;
            split_pack(w1a, w1b, h, l);
            WhB[8*136 + r2*136 + o] = h; WlB[8*136 + r2*136 + o] = l;
        }
        __syncthreads();

        unsigned bh[4][2], bl[4][2];
#pragma unroll
        for (int nt = 0; nt < 4; nt++) {
            int o = wn + nt*8 + grp;
            bh[nt][0] = Wh[tig*136 + o];     bh[nt][1] = Wh[(tig+4)*136 + o];
            bl[nt][0] = Wl[tig*136 + o];     bl[nt][1] = Wl[(tig+4)*136 + o];
        }
        int kgA = ch*16 + 2*tig;
#pragma unroll
        for (int mt = 0; mt < 2; mt++) {
            int b0 = wm + mt*16 + grp, b1 = b0 + 8;
            unsigned ah0, al0, ah1, al1, ah2, al2, ah3, al3;
            split_pack(xval(xr,b0,kgA),   xval(xr,b0,kgA+1), ah0, al0);
            split_pack(xval(xr,b1,kgA),   xval(xr,b1,kgA+1), ah1, al1);
            split_pack(xval(xr,b0,kgA+8), xval(xr,b0,kgA+9), ah2, al2);
            split_pack(xval(xr,b1,kgA+8), xval(xr,b1,kgA+9), ah3, al3);
#pragma unroll
            for (int nt = 0; nt < 4; nt++) {
                mma_bf16(acc[mt][nt][0], acc[mt][nt][1], acc[mt][nt][2], acc[mt][nt][3],
                         ah0, ah1, ah2, ah3, bh[nt][0], bh[nt][1]);
                mma_bf16(acc[mt][nt][0], acc[mt][nt][1], acc[mt][nt][2], acc[mt][nt][3],
                         ah0, ah1, ah2, ah3, bl[nt][0], bl[nt][1]);
                mma_bf16(acc[mt][nt][0], acc[mt][nt][1], acc[mt][nt][2], acc[mt][nt][3],
                         al0, al1, al2, al3, bh[nt][0], bh[nt][1]);
            }
        }
        __syncthreads();
    }

    // ---- finalize: sigmoid; z -> zh smem ; r -> d_r ----
    float* zh = xraw;   // reuse: [2][64][64]
    int n = n0 + nd;
#pragma unroll
    for (int mt = 0; mt < 2; mt++) {
#pragma unroll
        for (int nt = 0; nt < 4; nt++) {
            int o0 = wn + nt*8 + tig*2;
#pragma unroll
            for (int c = 0; c < 4; c++) {
                int b = wm + mt*16 + grp + ((c >> 1) ? 8 : 0);
                int o = o0 + (c & 1);
                float v = 1.f/(1.f + __expf(-(acc[mt][nt][c] + sbias[nd*128 + o])));
                if (o < HH) {
                    float hv = d_h[(size_t)(n*BB + b)*HH + o];
                    zh[nd*4096 + b*64 + o] = v*hv;
                } else {
                    d_r[(size_t)(n*BB + b)*HH + (o - HH)] = v;
                }
            }
        }
    }
    __syncthreads();

    // ---- repack Xu (packed planes) ----
    unsigned* Xuh = (unsigned*)d_Xu;
    unsigned* Xul = Xuh + (size_t)NP2*LCOLS;
    for (int idx = tid; idx < 4096; idx += 512) {
        int b = idx >> 6, o = idx & 63;
        unsigned h, l;
        split_pack(zh[idx], zh[4096 + idx], h, l);
        Xuh[(size_t)ip*LCOLS + b*CC + 1 + o] = h;
        Xul[(size_t)ip*LCOLS + b*CC + 1 + o] = l;
    }
    if (tid < 64) {
        unsigned h, l;
        split_pack(x[(size_t)(tid*TT + t)*NN + n0], x[(size_t)(tid*TT + t)*NN + n0 + 1], h, l);
        Xuh[(size_t)ip*LCOLS + tid*CC] = h;
        Xul[(size_t)ip*LCOLS + tid*CC] = l;
    }
}

__global__ __launch_bounds__(512) void update_epi_mma(
    const float* __restrict__ uW, const float* __restrict__ ub,
    float* __restrict__ out, const float* __restrict__ x, int t)
{
    extern __shared__ char smem[];
    float* xraw = (float*)smem;
    unsigned* WhB = (unsigned*)(smem + 2*3*LCOLS*4);             // [2][8][72]
    unsigned* WlB = WhB + 2*8*72;
    float* sbias  = (float*)(WlB + 2*8*72);                      // [2][64]
    float* nes    = sbias + 2*64;                                // [2][16]

    int tid = threadIdx.x;
    int ip = blockIdx.x;
    int n0 = ip*2;

    const unsigned* Xh  = (const unsigned*)d_Xu;  const unsigned* Xl  = Xh  + (size_t)NP2*LCOLS;
    const unsigned* Y1h = (const unsigned*)d_Y1u; const unsigned* Y1l = Y1h + (size_t)NP2*LCOLS;
    const unsigned* Y2h = (const unsigned*)d_Y2u; const unsigned* Y2l = Y2h + (size_t)NP2*LCOLS;

    for (int c = tid; c < LCOLS; c += 512) {
        size_t off = (size_t)ip*LCOLS + c;
        float x0, x1, y10, y11, y20, y21;
        unpack2(Xh[off],  Xl[off],  x0,  x1);
        unpack2(Y1h[off], Y1l[off], y10, y11);
        unpack2(Y2h[off], Y2l[off], y20, y21);
        xraw[c]           = x0;
        xraw[LCOLS + c]   = y10;
        xraw[2*LCOLS + c] = 2.f*y20 - x0;
        xraw[3*LCOLS + c] = x1;
        xraw[4*LCOLS + c] = y11;
        xraw[5*LCOLS + c] = 2.f*y21 - x1;
    }
    if (tid < 32) {
        int nd = tid >> 4, d = tid & 15;
        nes[nd*16 + d] = d_ne_u[(size_t)(t*NN + n0 + nd)*DD + d];
    }
    __syncthreads();

    if (tid < 128) {
        int nd = tid >> 6, o = tid & 63;
        float s = 0.f;
#pragma unroll
        for (int d = 0; d < DD; d++) s += nes[nd*16 + d]*ub[d*OU + o];
        sbias[nd*64 + o] = s;
    }

    int wid = tid >> 5, lane = tid & 31;
    int nd = wid >> 3, w8 = wid & 7;
    int wm = (w8 >> 2)*32, wn = (w8 & 3)*16;
    int grp = lane >> 2, tig = lane & 3;
    const float* xr = xraw + nd*(3*LCOLS);
    unsigned* Wh = WhB + nd*8*72;
    unsigned* Wl = WlB + nd*8*72;

    float acc[2][2][4];
#pragma unroll
    for (int i = 0; i < 2; i++)
#pragma unroll
        for (int j = 0; j < 2; j++)
#pragma unroll
            for (int c = 0; c < 4; c++) acc[i][j][c] = 0.f;

    for (int ch = 0; ch < 13; ch++) {
        {
            int r2 = tid >> 6, o = tid & 63;
            int kg0 = ch*16 + 2*r2, kg1 = kg0 + 1;
            float w0a = 0.f, w1a = 0.f, w0b = 0.f, w1b = 0.f;
            if (kg0 < 195) {
                int s = kg0/65, i = kg0 - s*65;
                const float* gp = uW + (size_t)(s*CC + i)*OU + o;
#pragma unroll
                for (int d = 0; d < DD; d++) {
                    float gv = gp[(size_t)d*(3*CC*OU)];
                    w0a += nes[d]*gv; w1a += nes[16+d]*gv;
                }
            }
            if (kg1 < 195) {
                int s = kg1/65, i = kg1 - s*65;
                const float* gp = uW + (size_t)(s*CC + i)*OU + o;
#pragma unroll
                for (int d = 0; d < DD; d++) {
                    float gv = gp[(size_t)d*(3*CC*OU)];
                    w0b += nes[d]*gv; w1b += nes[16+d]*gv;
                }
            }
            unsigned h, l;
            split_pack(w0a, w0b, h, l);
            WhB[r2*72 + o] = h; WlB[r2*72 + o] = l;
            split_pack(w1a, w1b, h, l);
            WhB[8*72 + r2*72 + o] = h; WlB[8*72 + r2*72 + o] = l;
        }
        __syncthreads();

        unsigned bh[2][2], bl[2][2];
#pragma unroll
        for (int nt = 0; nt < 2; nt++) {
            int o = wn + nt*8 + grp;
            bh[nt][0] = Wh[tig*72 + o];     bh[nt][1] = Wh[(tig+4)*72 + o];
            bl[nt][0] = Wl[tig*72 + o];     bl[nt][1] = Wl[(tig+4)*72 + o];
        }
        int kgA = ch*16 + 2*tig;
#pragma unroll
        for (int mt = 0; mt < 2; mt++) {
            int b0 = wm + mt*16 + grp, b1 = b0 + 8;
            unsigned ah0, al0, ah1, al1, ah2, al2, ah3, al3;
            split_pack(xval(xr,b0,kgA),   xval(xr,b0,kgA+1), ah0, al0);
            split_pack(xval(xr,b1,kgA),   xval(xr,b1,kgA+1), ah1, al1);
            split_pack(xval(xr,b0,kgA+8), xval(xr,b0,kgA+9), ah2, al2);
            split_pack(xval(xr,b1,kgA+8), xval(xr,b1,kgA+9), ah3, al3);
#pragma unroll
            for (int nt = 0; nt < 2; nt++) {
                mma_bf16(acc[mt][nt][0], acc[mt][nt][1], acc[mt][nt][2], acc[mt][nt][3],
                         ah0, ah1, ah2, ah3, bh[nt][0], bh[nt][1]);
                mma_bf16(acc[mt][nt][0], acc[mt][nt][1], acc[mt][nt][2], acc[mt][nt][3],
                         ah0, ah1, ah2, ah3, bl[nt][0], bl[nt][1]);
                mma_bf16(acc[mt][nt][0], acc[mt][nt][1], acc[mt][nt][2], acc[mt][nt][3],
                         al0, al1, al2, al3, bh[nt][0], bh[nt][1]);
            }
        }
        __syncthreads();
    }

    // ---- finalize: tanh + GRU; write h/out; stage hn for Xg repack ----
    float* zh = xraw;   // reuse: [2][64][64]
    int n = n0 + nd;
#pragma unroll
    for (int mt = 0; mt < 2; mt++) {
#pragma unroll
        for (int nt = 0; nt < 2; nt++) {
            int o0 = wn + nt*8 + tig*2;
#pragma unroll
            for (int c = 0; c < 4; c++) {
                int b = wm + mt*16 + grp + ((c >> 1) ? 8 : 0);
                int o = o0 + (c & 1);
                float hc = tanhf(acc[mt][nt][c] + sbias[nd*64 + o]);
                size_t idx = (size_t)(n*BB + b)*HH + o;
                float hv = d_h[idx];
                float rv = d_r[idx];
                float hn = rv*hv + (1.f - rv)*hc;
                d_h[idx] = hn;
                out[((size_t)(b*TT + t)*NN + n)*HH + o] = hn;
                zh[nd*4096 + b*64 + o] = hn;
            }
        }
    }
    __syncthreads();

    if (t + 1 < TT) {
        unsigned* Xgh = (unsigned*)d_Xg;
        unsigned* Xgl = Xgh + (size_t)NP2*LCOLS;
        for (int idx = tid; idx < 4096; idx += 512) {
            int b = idx >> 6, o = idx & 63;
            unsigned h, l;
            split_pack(zh[idx], zh[4096 + idx], h, l);
            Xgh[(size_t)ip*LCOLS + b*CC + 1 + o] = h;
            Xgl[(size_t)ip*LCOLS + b*CC + 1 + o] = l;
        }
        if (tid < 64) {
            unsigned h, l;
            split_pack(x[(size_t)(tid*TT + t+1)*NN + n0], x[(size_t)(tid*TT + t+1)*NN + n0 + 1], h, l);
            Xgh[(size_t)ip*LCOLS + tid*CC] = h;
            Xgl[(size_t)ip*LCOLS + tid*CC] = l;
        }
    }
}

// ---------------- host launcher ----------------
extern "C" void kernel_launch(void* const* d_in, const int* in_sizes, int n_in,
                              void* d_out, int out_size)
{
    const float *x = nullptr, *nodeE = nullptr, *timeE = nullptr;
    const float *gW = nullptr, *gb = nullptr, *uW = nullptr, *ub = nullptr;
    const float *ln16[4] = {nullptr, nullptr, nullptr, nullptr};
    int nln = 0;
    for (int i = 0; i < n_in; i++) {
        const float* p = (const float*)d_in[i];
        switch (in_sizes[i]) {
            case 786432: x = p; break;      // [64,12,1024,1]
            case 16384:  nodeE = p; break;  // [1024,16]
            case 192:    timeE = p; break;  // [12,16]
            case 399360: gW = p; break;     // [16,3,65,128]
            case 2048:   gb = p; break;     // [16,128]
            case 199680: uW = p; break;     // [16,3,65,64]
            case 1024:   ub = p; break;     // [16,64]
            case 16:     if (nln < 4) ln16[nln++] = p; break;
            default: break;
        }
    }
    const float* glg = ln16[0]; const float* glb = ln16[1];
    const float* ulg = ln16[2]; const float* ulb = ln16[3];
    float* out = (float*)d_out;

    cudaFuncSetAttribute(mma_gemm2,     cudaFuncAttributeMaxDynamicSharedMemorySize, GEMM_SMEM);
    cudaFuncSetAttribute(gate_epi_mma,  cudaFuncAttributeMaxDynamicSharedMemorySize, GATE_SMEM);
    cudaFuncSetAttribute(update_epi_mma, cudaFuncAttributeMaxDynamicSharedMemorySize, UPD_SMEM);

    zero_h_kernel<<<(NN*BB*HH + 255)/256, 256>>>();
    compute_ne_kernel<<<(TT*NN + 255)/256, 256>>>(nodeE, timeE, glg, glb, ulg, ulb);
    score_kernel<<<dim3(8, 8, 2*TT), 256>>>();
    softmax_kernel<<<dim3(128, TT, 2), 256>>>();
    pack0_kernel<<<((size_t)NP2*LCOLS + 255)/256, 256>>>(x);

    dim3 ggrid((LCOLS + 255)/256, NN/128);   // (17, 8) = 136 blocks -> 1 wave
    for (int t = 0; t < TT; t++) {
        mma_gemm2<<<ggrid, 256, GEMM_SMEM>>>(0, t, 0, 1);   // Y1g = Sg @ Xg
        mma_gemm2<<<ggrid, 256, GEMM_SMEM>>>(0, t, 1, 2);   // Y2g = Sg @ Y1g
        gate_epi_mma<<<NN/2, 512, GATE_SMEM>>>(gW, gb, x, t);
        mma_gemm2<<<ggrid, 256, GEMM_SMEM>>>(1, t, 3, 4);   // Y1u = Su @ Xu
        mma_gemm2<<<ggrid, 256, GEMM_SMEM>>>(1, t, 4, 5);   // Y2u = Su @ Y1u
        update_epi_mma<<<NN/2, 512, UPD_SMEM>>>(uW, ub, out, x, t);
    }
}

// round 7
// speedup vs baseline: 1.9996x; 1.0052x over previous
#include <cuda_runtime.h>
#include <cuda_bf16.h>
#include <math.h>

// Problem constants
#define NN 1024   // nodes
#define BB 64     // batch
#define TT 12     // time steps
#define DD 16     // embedding dim
#define HH 64     // hidden
#define CC 65     // C_IN + H
#define LCOLS (BB*CC)   // 4160
#define OG 128    // gate output (2H)
#define OU 64     // update output (H)
#define NP2 512   // node pairs (NN/2)
#define K2T 104   // epilogue K pairs (208/2)

// ---------------- scratch (static device allocations) ----------------
__device__ float d_ne_g[TT*NN*DD];
__device__ float d_ne_u[TT*NN*DD];
__device__ float d_Sg[(size_t)TT*NN*NN];   // scores -> packed bf16 hi/lo after softmax
__device__ float d_Su[(size_t)TT*NN*NN];
__device__ float d_h [NN*BB*HH];           // [N,B,H] fp32
__device__ float d_r [NN*BB*HH];           // fp32
// PACKED bf16 hi/lo planes: [0,512*LCOLS) hi uints [k2][col], [512*LCOLS,...) lo
__device__ float d_Xg [(size_t)NN*LCOLS];
__device__ float d_Y1g[(size_t)NN*LCOLS];
__device__ float d_Y2g[(size_t)NN*LCOLS];
__device__ float d_Xu [(size_t)NN*LCOLS];
__device__ float d_Y1u[(size_t)NN*LCOLS];
__device__ float d_Y2u[(size_t)NN*LCOLS];
// per-step per-node weight banks, packed bf16 hi/lo
#define WGSZ ((size_t)NN*K2T*OG)
#define WUSZ ((size_t)NN*K2T*OU)
__device__ unsigned d_Wg[2*WGSZ];   // 109 MB
__device__ unsigned d_Wu[2*WUSZ];   // 55 MB

// ---------------- helpers ----------------
__device__ __forceinline__ unsigned pack_bf16(float v0, float v1)
{
    __nv_bfloat162 t = __floats2bfloat162_rn(v0, v1);
    return *(unsigned*)&t;
}
__device__ __forceinline__ void split_pack(float v0, float v1, unsigned& hi, unsigned& lo)
{
    __nv_bfloat16 h0 = __float2bfloat16(v0);
    __nv_bfloat16 h1 = __float2bfloat16(v1);
    float r0 = v0 - __bfloat162float(h0);
    float r1 = v1 - __bfloat162float(h1);
    hi = ((unsigned)__bfloat16_as_ushort(h1) << 16) | (unsigned)__bfloat16_as_ushort(h0);
    lo = pack_bf16(r0, r1);
}
__device__ __forceinline__ void unpack2(unsigned h, unsigned l, float& a, float& b)
{
    __nv_bfloat162 hh = *reinterpret_cast<__nv_bfloat162*>(&h);
    __nv_bfloat162 ll = *reinterpret_cast<__nv_bfloat162*>(&l);
    a = __bfloat162float(hh.x) + __bfloat162float(ll.x);
    b = __bfloat162float(hh.y) + __bfloat162float(ll.y);
}
__device__ __forceinline__ void mma_bf16(float& c0, float& c1, float& c2, float& c3,
    unsigned a0, unsigned a1, unsigned a2, unsigned a3, unsigned b0, unsigned b1)
{
    asm volatile("mma.sync.aligned.m16n8k16.row.col.f32.bf16.bf16.f32 "
        "{%0,%1,%2,%3}, {%4,%5,%6,%7}, {%8,%9}, {%0,%1,%2,%3};\n"
        : "+f"(c0), "+f"(c1), "+f"(c2), "+f"(c3)
        : "r"(a0), "r"(a1), "r"(a2), "r"(a3), "r"(b0), "r"(b1));
}

// ---------------- h = 0 ----------------
__global__ void zero_h_kernel()
{
    int i = blockIdx.x*blockDim.x + threadIdx.x;
    if (i < NN*BB*HH) d_h[i] = 0.f;
}

// ---------------- layernormed node+time embeddings, all t ----------------
__global__ void compute_ne_kernel(const float* __restrict__ nodeE,
                                  const float* __restrict__ timeE,
                                  const float* __restrict__ gg, const float* __restrict__ gbeta,
                                  const float* __restrict__ ug, const float* __restrict__ ubeta)
{
    int idx = blockIdx.x*blockDim.x + threadIdx.x;   // t*NN + n
    if (idx >= TT*NN) return;
    int t = idx >> 10;
    int n = idx & (NN-1);
    float v[DD];
    float mu = 0.f;
#pragma unroll
    for (int d = 0; d < DD; d++) { v[d] = nodeE[n*DD+d] + timeE[t*DD+d]; mu += v[d]; }
    mu *= (1.f/DD);
    float var = 0.f;
#pragma unroll
    for (int d = 0; d < DD; d++) { float dv = v[d]-mu; var += dv*dv; }
    var *= (1.f/DD);
    float inv = 1.f / sqrtf(var + 1e-12f);
#pragma unroll
    for (int d = 0; d < DD; d++) {
        float nv = (v[d]-mu)*inv;
        d_ne_g[idx*DD+d] = nv*gg[d] + gbeta[d];
        d_ne_u[idx*DD+d] = nv*ug[d] + ubeta[d];
    }
}

// ---------------- scores G = ne @ ne^T ----------------
__global__ __launch_bounds__(256) void score_kernel()
{
    int z = blockIdx.z;
    int which = (z >= TT) ? 1 : 0;
    int t = which ? (z - TT) : z;
    const float* __restrict__ ne = (which ? d_ne_u : d_ne_g) + t*NN*DD;
    float* __restrict__ G = (which ? d_Su : d_Sg) + (size_t)t*NN*NN;
    __shared__ float Rt[DD][132];
    __shared__ float Ct[DD][132];
    int tid = threadIdx.x;
#pragma unroll
    for (int rep = 0; rep < 2; rep++) {
        int f = tid + rep*256;
        int r = f >> 2, q = (f & 3) << 2;
        float4 v = *(const float4*)(ne + (blockIdx.y*128 + r)*DD + q);
        Rt[q+0][r] = v.x; Rt[q+1][r] = v.y; Rt[q+2][r] = v.z; Rt[q+3][r] = v.w;
        float4 w = *(const float4*)(ne + (blockIdx.x*128 + r)*DD + q);
        Ct[q+0][r] = w.x; Ct[q+1][r] = w.y; Ct[q+2][r] = w.z; Ct[q+3][r] = w.w;
    }
    __syncthreads();
    int ty = tid >> 4, tx = tid & 15;
    int r0 = ty*8, c0 = tx*8;
    float acc[8][8];
#pragma unroll
    for (int i = 0; i < 8; i++)
#pragma unroll
        for (int j = 0; j < 8; j++) acc[i][j] = 0.f;
#pragma unroll
    for (int k = 0; k < DD; k++) {
        float rv[8], cv[8];
        *(float4*)&rv[0] = *(const float4*)&Rt[k][r0];
        *(float4*)&rv[4] = *(const float4*)&Rt[k][r0+4];
        *(float4*)&cv[0] = *(const float4*)&Ct[k][c0];
        *(float4*)&cv[4] = *(const float4*)&Ct[k][c0+4];
#pragma unroll
        for (int i = 0; i < 8; i++)
#pragma unroll
            for (int j = 0; j < 8; j++) acc[i][j] += rv[i]*cv[j];
    }
#pragma unroll
    for (int i = 0; i < 8; i++) {
        float* gp = G + (size_t)(blockIdx.y*128 + r0 + i)*NN + blockIdx.x*128 + c0;
        *(float4*)gp     = make_float4(acc[i][0], acc[i][1], acc[i][2], acc[i][3]);
        *(float4*)(gp+4) = make_float4(acc[i][4], acc[i][5], acc[i][6], acc[i][7]);
    }
}

// ---------------- row softmax, output packed bf16 hi/lo (in-place) ----------------
__global__ __launch_bounds__(256) void softmax_kernel()
{
    int which = blockIdx.z, t = blockIdx.y;
    float* S = (which ? d_Su : d_Sg) + (size_t)t*NN*NN;
    int warp = threadIdx.x >> 5, lane = threadIdx.x & 31;
    int row = blockIdx.x*8 + warp;
    float4* p = (float4*)(S + (size_t)row*NN);
    float4 v[8];
    float mx = -1e30f;
#pragma unroll
    for (int i = 0; i < 8; i++) {
        v[i] = p[lane + i*32];
        mx = fmaxf(mx, fmaxf(fmaxf(v[i].x, v[i].y), fmaxf(v[i].z, v[i].w)));
    }
#pragma unroll
    for (int o = 16; o > 0; o >>= 1) mx = fmaxf(mx, __shfl_xor_sync(0xffffffffu, mx, o));
    float sum = 0.f;
#pragma unroll
    for (int i = 0; i < 8; i++) {
        v[i].x = __expf(v[i].x - mx); v[i].y = __expf(v[i].y - mx);
        v[i].z = __expf(v[i].z - mx); v[i].w = __expf(v[i].w - mx);
        sum += v[i].x + v[i].y + v[i].z + v[i].w;
    }
#pragma unroll
    for (int o = 16; o > 0; o >>= 1) sum += __shfl_xor_sync(0xffffffffu, sum, o);
    float inv = 1.f / sum;
    unsigned* ur = (unsigned*)(S + (size_t)row*NN);
#pragma unroll
    for (int i = 0; i < 8; i++) {
        float a = v[i].x*inv, b = v[i].y*inv, c = v[i].z*inv, d = v[i].w*inv;
        unsigned h0, l0, h1, l1;
        split_pack(a, b, h0, l0);
        split_pack(c, d, h1, l1);
        int j0 = 2*(lane + i*32);
        ur[j0]       = h0; ur[j0+1]       = h1;
        ur[512 + j0] = l0; ur[512 + j0+1] = l1;
    }
}

// ---------------- pack Xg at t=0 (packed planes) ----------------
__global__ void pack0_kernel(const float* __restrict__ x)
{
    int idx = blockIdx.x*blockDim.x + threadIdx.x;
    if (idx >= NP2*LCOLS) return;
    int i = idx / LCOLS;
    int c = idx - i*LCOLS;
    int b = c / CC, cc = c - b*CC;
    unsigned h = 0, l = 0;
    if (cc == 0)
        split_pack(x[(size_t)(b*TT)*NN + 2*i], x[(size_t)(b*TT)*NN + 2*i + 1], h, l);
    unsigned* Xh = (unsigned*)d_Xg;
    Xh[idx] = h;
    Xh[(size_t)NP2*LCOLS + idx] = l;
}

// ---------------- per-node weight banks (per step) ----------------
// d_Wg[(n*104 + r2)*128 + o] = split_pack(W(n,2r2,o), W(n,2r2+1,o)), lo at +WGSZ
__global__ __launch_bounds__(256) void wgen_gate(const float* __restrict__ gW, int t)
{
    __shared__ float ne8[8][16];
    int tid = threadIdx.x;
    int n0 = blockIdx.x*8;
    if (tid < 128) {
        int n = tid >> 4, d = tid & 15;
        ne8[n][d] = d_ne_g[(size_t)(t*NN + n0 + n)*DD + d];
    }
    __syncthreads();
    int o = tid & 127, half = tid >> 7;
    for (int r2 = half; r2 < K2T; r2 += 2) {
        int kg0 = 2*r2, kg1 = kg0 + 1;
        float g0[DD], g1[DD];
        if (kg0 < 195) {
            int s = kg0/65, i = kg0 - s*65;
            const float* gp = gW + (size_t)(s*CC + i)*OG + o;
#pragma unroll
            for (int d = 0; d < DD; d++) g0[d] = gp[(size_t)d*(3*CC*OG)];
        } else {
#pragma unroll
            for (int d = 0; d < DD; d++) g0[d] = 0.f;
        }
        if (kg1 < 195) {
            int s = kg1/65, i = kg1 - s*65;
            const float* gp = gW + (size_t)(s*CC + i)*OG + o;
#pragma unroll
            for (int d = 0; d < DD; d++) g1[d] = gp[(size_t)d*(3*CC*OG)];
        } else {
#pragma unroll
            for (int d = 0; d < DD; d++) g1[d] = 0.f;
        }
#pragma unroll
        for (int n = 0; n < 8; n++) {
            float w0 = 0.f, w1 = 0.f;
#pragma unroll
            for (int d = 0; d < DD; d++) {
                float nv = ne8[n][d];
                w0 += nv*g0[d]; w1 += nv*g1[d];
            }
            unsigned h, l;
            split_pack(w0, w1, h, l);
            size_t a = ((size_t)(n0+n)*K2T + r2)*OG + o;
            d_Wg[a] = h;
            d_Wg[WGSZ + a] = l;
        }
    }
}

__global__ __launch_bounds__(256) void wgen_update(const float* __restrict__ uW, int t)
{
    __shared__ float ne8[8][16];
    int tid = threadIdx.x;
    int n0 = blockIdx.x*8;
    if (tid < 128) {
        int n = tid >> 4, d = tid & 15;
        ne8[n][d] = d_ne_u[(size_t)(t*NN + n0 + n)*DD + d];
    }
    __syncthreads();
    int o = tid & 63, q = tid >> 6;
    for (int r2 = q; r2 < K2T; r2 += 4) {
        int kg0 = 2*r2, kg1 = kg0 + 1;
        float g0[DD], g1[DD];
        if (kg0 < 195) {
            int s = kg0/65, i = kg0 - s*65;
            const float* gp = uW + (size_t)(s*CC + i)*OU + o;
#pragma unroll
            for (int d = 0; d < DD; d++) g0[d] = gp[(size_t)d*(3*CC*OU)];
        } else {
#pragma unroll
            for (int d = 0; d < DD; d++) g0[d] = 0.f;
        }
        if (kg1 < 195) {
            int s = kg1/65, i = kg1 - s*65;
            const float* gp = uW + (size_t)(s*CC + i)*OU + o;
#pragma unroll
            for (int d = 0; d < DD; d++) g1[d] = gp[(size_t)d*(3*CC*OU)];
        } else {
#pragma unroll
            for (int d = 0; d < DD; d++) g1[d] = 0.f;
        }
#pragma unroll
        for (int n = 0; n < 8; n++) {
            float w0 = 0.f, w1 = 0.f;
#pragma unroll
            for (int d = 0; d < DD; d++) {
                float nv = ne8[n][d];
                w0 += nv*g0[d]; w1 += nv*g1[d];
            }
            unsigned h, l;
            split_pack(w0, w1, h, l);
            size_t a = ((size_t)(n0+n)*K2T + r2)*OU + o;
            d_Wu[a] = h;
            d_Wu[WUSZ + a] = l;
        }
    }
}

// ---------------- bf16x3 GEMM: C = S @ B  (all operands packed bf16 hi/lo) ----------------
__device__ __forceinline__ const float* gemm_src(int id)
{
    switch (id) {
        case 0: return d_Xg;  case 1: return d_Y1g; case 2: return d_Y2g;
        case 3: return d_Xu;  case 4: return d_Y1u; default: return d_Y2u;
    }
}
__device__ __forceinline__ float* gemm_dst(int id)
{
    switch (id) {
        case 1: return d_Y1g; case 2: return d_Y2g;
        case 4: return d_Y1u; default: return d_Y2u;
    }
}

#define APAD 136
#define BPAD 264
#define GEMM_SMEM ((2*8*APAD*2 + 2*8*BPAD*2)*4)   // 51200 bytes

__global__ __launch_bounds__(256) void mma_gemm2(int su, int t, int bsel, int csel)
{
    extern __shared__ unsigned sm[];
    unsigned* AhS = sm;
    unsigned* AlS = AhS + 2*8*APAD;
    unsigned* BhS = AlS + 2*8*APAD;
    unsigned* BlS = BhS + 2*8*BPAD;

    const unsigned* Apk = (const unsigned*)((su ? d_Su : d_Sg) + (size_t)t*NN*NN);
    const unsigned* Bgh = (const unsigned*)gemm_src(bsel);
    const unsigned* Bgl = Bgh + (size_t)NP2*LCOLS;
    unsigned* Cgh = (unsigned*)gemm_dst(csel);
    unsigned* Cgl = Cgh + (size_t)NP2*LCOLS;

    int tid = threadIdx.x, warp = tid >> 5, lane = tid & 31;
    int wm = (warp >> 2)*64, wn = (warp & 3)*64;
    int grp = lane >> 2, tig = lane & 3;

    int aRow = tid & 127, aHalf = tid >> 7;
    const unsigned* ApH = Apk + (size_t)(blockIdx.y*128 + aRow)*1024 + aHalf*4;

    int bK2 = tid >> 5, bC4 = tid & 31;
    int colr0 = blockIdx.x*256 + bC4*4;
    int colr1 = colr0 + 128;
    bool ok0 = colr0 < LCOLS, ok1 = colr1 < LCOLS;

    float acc[4][8][4];
#pragma unroll
    for (int i = 0; i < 4; i++)
#pragma unroll
        for (int j = 0; j < 8; j++)
#pragma unroll
            for (int c = 0; c < 4; c++) acc[i][j][c] = 0.f;

    const uint4 z4 = make_uint4(0,0,0,0);
    {
        uint4 h = *(const uint4*)ApH;
        uint4 l = *(const uint4*)(ApH + 512);
        int ab = aHalf*4*APAD;
        AhS[ab + 0*APAD + aRow] = h.x; AhS[ab + 1*APAD + aRow] = h.y;
        AhS[ab + 2*APAD + aRow] = h.z; AhS[ab + 3*APAD + aRow] = h.w;
        AlS[ab + 0*APAD + aRow] = l.x; AlS[ab + 1*APAD + aRow] = l.y;
        AlS[ab + 2*APAD + aRow] = l.z; AlS[ab + 3*APAD + aRow] = l.w;
        size_t brow = (size_t)bK2*LCOLS;
        uint4 b0h = ok0 ? *(const uint4*)(Bgh + brow + colr0) : z4;
        uint4 b1h = ok1 ? *(const uint4*)(Bgh + brow + colr1) : z4;
        uint4 b0l = ok0 ? *(const uint4*)(Bgl + brow + colr0) : z4;
        uint4 b1l = ok1 ? *(const uint4*)(Bgl + brow + colr1) : z4;
        int bb = bK2*BPAD;
        *(uint4*)&BhS[bb + bC4*4]       = b0h;
        *(uint4*)&BhS[bb + 128 + bC4*4] = b1h;
        *(uint4*)&BlS[bb + bC4*4]       = b0l;
        *(uint4*)&BlS[bb + 128 + bC4*4] = b1l;
    }
    __syncthreads();

    int buf = 0;
    for (int k0 = 0; k0 < 1024; k0 += 16) {
        bool pf = (k0 + 16) < 1024;
        uint4 ph, pl, pb0h, pb1h, pb0l, pb1l;
        if (pf) {
            int k2g = (k0 + 16) >> 1;
            ph = *(const uint4*)(ApH + k2g);
            pl = *(const uint4*)(ApH + 512 + k2g);
            size_t brow = (size_t)(k2g + bK2)*LCOLS;
            pb0h = ok0 ? *(const uint4*)(Bgh + brow + colr0) : z4;
            pb1h = ok1 ? *(const uint4*)(Bgh + brow + colr1) : z4;
            pb0l = ok0 ? *(const uint4*)(Bgl + brow + colr0) : z4;
            pb1l = ok1 ? *(const uint4*)(Bgl + brow + colr1) : z4;
        }
        const unsigned* AhB = AhS + buf*8*APAD;
        const unsigned* AlB = AlS + buf*8*APAD;
        const unsigned* BhB = BhS + buf*8*BPAD;
        const unsigned* BlB = BlS + buf*8*BPAD;

        unsigned bh[8][2], bl[8][2];
#pragma unroll
        for (int nt = 0; nt < 8; nt++) {
            int o = wn + nt*8 + grp;
            bh[nt][0] = BhB[tig*BPAD + o];     bh[nt][1] = BhB[(tig+4)*BPAD + o];
            bl[nt][0] = BlB[tig*BPAD + o];     bl[nt][1] = BlB[(tig+4)*BPAD + o];
        }
#pragma unroll
        for (int mt = 0; mt < 4; mt++) {
            int m = wm + mt*16;
            unsigned ah0 = AhB[tig*APAD + m+grp];
            unsigned ah1 = AhB[tig*APAD + m+grp+8];
            unsigned ah2 = AhB[(tig+4)*APAD + m+grp];
            unsigned ah3 = AhB[(tig+4)*APAD + m+grp+8];
            unsigned al0 = AlB[tig*APAD + m+grp];
            unsigned al1 = AlB[tig*APAD + m+grp+8];
            unsigned al2 = AlB[(tig+4)*APAD + m+grp];
            unsigned al3 = AlB[(tig+4)*APAD + m+grp+8];
#pragma unroll
            for (int nt = 0; nt < 8; nt++) {
                mma_bf16(acc[mt][nt][0], acc[mt][nt][1], acc[mt][nt][2], acc[mt][nt][3],
                         ah0, ah1, ah2, ah3, bh[nt][0], bh[nt][1]);
                mma_bf16(acc[mt][nt][0], acc[mt][nt][1], acc[mt][nt][2], acc[mt][nt][3],
                         ah0, ah1, ah2, ah3, bl[nt][0], bl[nt][1]);
                mma_bf16(acc[mt][nt][0], acc[mt][nt][1], acc[mt][nt][2], acc[mt][nt][3],
                         al0, al1, al2, al3, bh[nt][0], bh[nt][1]);
            }
        }
        if (pf) {
            int nb = buf ^ 1;
            int ab = nb*8*APAD + aHalf*4*APAD;
            AhS[ab + 0*APAD + aRow] = ph.x; AhS[ab + 1*APAD + aRow] = ph.y;
            AhS[ab + 2*APAD + aRow] = ph.z; AhS[ab + 3*APAD + aRow] = ph.w;
            AlS[ab + 0*APAD + aRow] = pl.x; AlS[ab + 1*APAD + aRow] = pl.y;
            AlS[ab + 2*APAD + aRow] = pl.z; AlS[ab + 3*APAD + aRow] = pl.w;
            int bb = nb*8*BPAD + bK2*BPAD;
            *(uint4*)&BhS[bb + bC4*4]       = pb0h;
            *(uint4*)&BhS[bb + 128 + bC4*4] = pb1h;
            *(uint4*)&BlS[bb + bC4*4]       = pb0l;
            *(uint4*)&BlS[bb + 128 + bC4*4] = pb1l;
            __syncthreads();
            buf = nb;
        }
    }

#pragma unroll
    for (int mt = 0; mt < 4; mt++) {
        int rowbase = blockIdx.y*128 + wm + mt*16;
#pragma unroll
        for (int nt = 0; nt < 8; nt++) {
            float c0 = acc[mt][nt][0], c1 = acc[mt][nt][1];
            float c2 = acc[mt][nt][2], c3 = acc[mt][nt][3];
            float p0 = __shfl_xor_sync(0xffffffffu, c0, 4);
            float p1 = __shfl_xor_sync(0xffffffffu, c1, 4);
            float p2 = __shfl_xor_sync(0xffffffffu, c2, 4);
            float p3 = __shfl_xor_sync(0xffffffffu, c3, 4);
            unsigned h0, l0, h1, l1;
            int k2;
            if (!(grp & 1)) {
                split_pack(c0, p0, h0, l0);
                split_pack(c1, p1, h1, l1);
                k2 = (rowbase + grp) >> 1;
            } else {
                split_pack(p2, c2, h0, l0);
                split_pack(p3, c3, h1, l1);
                k2 = (rowbase + 7 + grp) >> 1;
            }
            int col0 = blockIdx.x*256 + wn + nt*8 + tig*2;
            if (col0 < LCOLS) {
                *(uint2*)&Cgh[(size_t)k2*LCOLS + col0] = make_uint2(h0, h1);
                *(uint2*)&Cgl[(size_t)k2*LCOLS + col0] = make_uint2(l0, l1);
            }
        }
    }
}

// ================= tensor-core GCN epilogues (2 nodes / block, 512 threads) =================
#define GATE_SMEM (2*3*LCOLS*4 + 2*8*136*4*2 + 2*128*4 + 2*16*4)
#define UPD_SMEM  (2*3*LCOLS*4 + 2*8*72*4*2  + 2*64*4  + 2*16*4)

__device__ __forceinline__ float xval(const float* xr, int b, int kg)
{
    if (kg >= 195) return 0.f;
    int s = kg / 65;
    int i = kg - s*65;
    return xr[s*LCOLS + b*CC + i];
}

__global__ __launch_bounds__(512) void gate_epi_mma(
    const float* __restrict__ gb, const float* __restrict__ x, int t)
{
    extern __shared__ char smem[];
    float* xraw = (float*)smem;                                  // [2][3*LCOLS]
    unsigned* WhB = (unsigned*)(smem + 2*3*LCOLS*4);             // [2][8][136]
    unsigned* WlB = WhB + 2*8*136;
    float* sbias  = (float*)(WlB + 2*8*136);                     // [2][128]
    float* nes    = sbias + 2*128;                               // [2][16]

    int tid = threadIdx.x;
    int ip = blockIdx.x;
    int n0 = ip*2;

    const unsigned* Xh  = (const unsigned*)d_Xg;  const unsigned* Xl  = Xh  + (size_t)NP2*LCOLS;
    const unsigned* Y1h = (const unsigned*)d_Y1g; const unsigned* Y1l = Y1h + (size_t)NP2*LCOLS;
    const unsigned* Y2h = (const unsigned*)d_Y2g; const unsigned* Y2l = Y2h + (size_t)NP2*LCOLS;

    for (int c = tid; c < LCOLS; c += 512) {
        size_t off = (size_t)ip*LCOLS + c;
        float x0, x1, y10, y11, y20, y21;
        unpack2(Xh[off],  Xl[off],  x0,  x1);
        unpack2(Y1h[off], Y1l[off], y10, y11);
        unpack2(Y2h[off], Y2l[off], y20, y21);
        xraw[c]           = x0;
        xraw[LCOLS + c]   = y10;
        xraw[2*LCOLS + c] = 2.f*y20 - x0;
        xraw[3*LCOLS + c] = x1;
        xraw[4*LCOLS + c] = y11;
        xraw[5*LCOLS + c] = 2.f*y21 - x1;
    }
    if (tid < 32) {
        int nd = tid >> 4, d = tid & 15;
        nes[nd*16 + d] = d_ne_g[(size_t)(t*NN + n0 + nd)*DD + d];
    }
    __syncthreads();

    if (tid < 256) {
        int nd = tid >> 7, o = tid & 127;
        float s = 0.f;
#pragma unroll
        for (int d = 0; d < DD; d++) s += nes[nd*16 + d]*gb[d*OG + o];
        sbias[nd*128 + o] = s;
    }

    int wid = tid >> 5, lane = tid & 31;
    int nd = wid >> 3, w8 = wid & 7;
    int wm = (w8 >> 2)*32, wn = (w8 & 3)*32;
    int grp = lane >> 2, tig = lane & 3;
    const float* xr = xraw + nd*(3*LCOLS);
    unsigned* Wh = WhB + nd*8*136;
    unsigned* Wl = WlB + nd*8*136;

    // staging map for weight chunks
    int snd = tid >> 8, sr2 = (tid >> 5) & 7, so4 = (tid & 31) << 2;

    float acc[2][4][4];
#pragma unroll
    for (int i = 0; i < 2; i++)
#pragma unroll
        for (int j = 0; j < 4; j++)
#pragma unroll
            for (int c = 0; c < 4; c++) acc[i][j][c] = 0.f;

    for (int ch = 0; ch < 13; ch++) {
        // ---- stage precomputed weight chunk ----
        {
            size_t a = ((size_t)(n0 + snd)*K2T + ch*8 + sr2)*OG + so4;
            uint4 h4 = *(const uint4*)&d_Wg[a];
            uint4 l4 = *(const uint4*)&d_Wg[WGSZ + a];
            *(uint4*)&WhB[snd*8*136 + sr2*136 + so4] = h4;
            *(uint4*)&WlB[snd*8*136 + sr2*136 + so4] = l4;
        }
        __syncthreads();

        unsigned bh[4][2], bl[4][2];
#pragma unroll
        for (int nt = 0; nt < 4; nt++) {
            int o = wn + nt*8 + grp;
            bh[nt][0] = Wh[tig*136 + o];     bh[nt][1] = Wh[(tig+4)*136 + o];
            bl[nt][0] = Wl[tig*136 + o];     bl[nt][1] = Wl[(tig+4)*136 + o];
        }
        int kgA = ch*16 + 2*tig;
#pragma unroll
        for (int mt = 0; mt < 2; mt++) {
            int b0 = wm + mt*16 + grp, b1 = b0 + 8;
            unsigned ah0, al0, ah1, al1, ah2, al2, ah3, al3;
            split_pack(xval(xr,b0,kgA),   xval(xr,b0,kgA+1), ah0, al0);
            split_pack(xval(xr,b1,kgA),   xval(xr,b1,kgA+1), ah1, al1);
            split_pack(xval(xr,b0,kgA+8), xval(xr,b0,kgA+9), ah2, al2);
            split_pack(xval(xr,b1,kgA+8), xval(xr,b1,kgA+9), ah3, al3);
#pragma unroll
            for (int nt = 0; nt < 4; nt++) {
                mma_bf16(acc[mt][nt][0], acc[mt][nt][1], acc[mt][nt][2], acc[mt][nt][3],
                         ah0, ah1, ah2, ah3, bh[nt][0], bh[nt][1]);
                mma_bf16(acc[mt][nt][0], acc[mt][nt][1], acc[mt][nt][2], acc[mt][nt][3],
                         ah0, ah1, ah2, ah3, bl[nt][0], bl[nt][1]);
                mma_bf16(acc[mt][nt][0], acc[mt][nt][1], acc[mt][nt][2], acc[mt][nt][3],
                         al0, al1, al2, al3, bh[nt][0], bh[nt][1]);
            }
        }
        __syncthreads();
    }

    // ---- finalize: sigmoid; z -> zh smem ; r -> d_r ----
    float* zh = xraw;   // reuse: [2][64][64]
    int n = n0 + nd;
#pragma unroll
    for (int mt = 0; mt < 2; mt++) {
#pragma unroll
        for (int nt = 0; nt < 4; nt++) {
            int o0 = wn + nt*8 + tig*2;
#pragma unroll
            for (int c = 0; c < 4; c++) {
                int b = wm + mt*16 + grp + ((c >> 1) ? 8 : 0);
                int o = o0 + (c & 1);
                float v = 1.f/(1.f + __expf(-(acc[mt][nt][c] + sbias[nd*128 + o])));
                if (o < HH) {
                    float hv = d_h[(size_t)(n*BB + b)*HH + o];
                    zh[nd*4096 + b*64 + o] = v*hv;
                } else {
                    d_r[(size_t)(n*BB + b)*HH + (o - HH)] = v;
                }
            }
        }
    }
    __syncthreads();

    unsigned* Xuh = (unsigned*)d_Xu;
    unsigned* Xul = Xuh + (size_t)NP2*LCOLS;
    for (int idx = tid; idx < 4096; idx += 512) {
        int b = idx >> 6, o = idx & 63;
        unsigned h, l;
        split_pack(zh[idx], zh[4096 + idx], h, l);
        Xuh[(size_t)ip*LCOLS + b*CC + 1 + o] = h;
        Xul[(size_t)ip*LCOLS + b*CC + 1 + o] = l;
    }
    if (tid < 64) {
        unsigned h, l;
        split_pack(x[(size_t)(tid*TT + t)*NN + n0], x[(size_t)(tid*TT + t)*NN + n0 + 1], h, l);
        Xuh[(size_t)ip*LCOLS + tid*CC] = h;
        Xul[(size_t)ip*LCOLS + tid*CC] = l;
    }
}

__global__ __launch_bounds__(512) void update_epi_mma(
    const float* __restrict__ ub,
    float* __restrict__ out, const float* __restrict__ x, int t)
{
    extern __shared__ char smem[];
    float* xraw = (float*)smem;
    unsigned* WhB = (unsigned*)(smem + 2*3*LCOLS*4);             // [2][8][72]
    unsigned* WlB = WhB + 2*8*72;
    float* sbias  = (float*)(WlB + 2*8*72);                      // [2][64]
    float* nes    = sbias + 2*64;                                // [2][16]

    int tid = threadIdx.x;
    int ip = blockIdx.x;
    int n0 = ip*2;

    const unsigned* Xh  = (const unsigned*)d_Xu;  const unsigned* Xl  = Xh  + (size_t)NP2*LCOLS;
    const unsigned* Y1h = (const unsigned*)d_Y1u; const unsigned* Y1l = Y1h + (size_t)NP2*LCOLS;
    const unsigned* Y2h = (const unsigned*)d_Y2u; const unsigned* Y2l = Y2h + (size_t)NP2*LCOLS;

    for (int c = tid; c < LCOLS; c += 512) {
        size_t off = (size_t)ip*LCOLS + c;
        float x0, x1, y10, y11, y20, y21;
        unpack2(Xh[off],  Xl[off],  x0,  x1);
        unpack2(Y1h[off], Y1l[off], y10, y11);
        unpack2(Y2h[off], Y2l[off], y20, y21);
        xraw[c]           = x0;
        xraw[LCOLS + c]   = y10;
        xraw[2*LCOLS + c] = 2.f*y20 - x0;
        xraw[3*LCOLS + c] = x1;
        xraw[4*LCOLS + c] = y11;
        xraw[5*LCOLS + c] = 2.f*y21 - x1;
    }
    if (tid < 32) {
        int nd = tid >> 4, d = tid & 15;
        nes[nd*16 + d] = d_ne_u[(size_t)(t*NN + n0 + nd)*DD + d];
    }
    __syncthreads();

    if (tid < 128) {
        int nd = tid >> 6, o = tid & 63;
        float s = 0.f;
#pragma unroll
        for (int d = 0; d < DD; d++) s += nes[nd*16 + d]*ub[d*OU + o];
        sbias[nd*64 + o] = s;
    }

    int wid = tid >> 5, lane = tid & 31;
    int nd = wid >> 3, w8 = wid & 7;
    int wm = (w8 >> 2)*32, wn = (w8 & 3)*16;
    int grp = lane >> 2, tig = lane & 3;
    const float* xr = xraw + nd*(3*LCOLS);
    unsigned* Wh = WhB + nd*8*72;
    unsigned* Wl = WlB + nd*8*72;

    // staging map: 512 threads cover 2 nodes x 8 r2 x 64 o as uint2... use first 512 slots of uints*?
    int snd = tid >> 8, srem = tid & 255, sr2 = srem >> 5, so2 = (srem & 31) << 1;

    float acc[2][2][4];
#pragma unroll
    for (int i = 0; i < 2; i++)
#pragma unroll
        for (int j = 0; j < 2; j++)
#pragma unroll
            for (int c = 0; c < 4; c++) acc[i][j][c] = 0.f;

    for (int ch = 0; ch < 13; ch++) {
        {
            size_t a = ((size_t)(n0 + snd)*K2T + ch*8 + sr2)*OU + so2;
            uint2 h2 = *(const uint2*)&d_Wu[a];
            uint2 l2 = *(const uint2*)&d_Wu[WUSZ + a];
            *(uint2*)&WhB[snd*8*72 + sr2*72 + so2] = h2;
            *(uint2*)&WlB[snd*8*72 + sr2*72 + so2] = l2;
        }
        __syncthreads();

        unsigned bh[2][2], bl[2][2];
#pragma unroll
        for (int nt = 0; nt < 2; nt++) {
            int o = wn + nt*8 + grp;
            bh[nt][0] = Wh[tig*72 + o];     bh[nt][1] = Wh[(tig+4)*72 + o];
            bl[nt][0] = Wl[tig*72 + o];     bl[nt][1] = Wl[(tig+4)*72 + o];
        }
        int kgA = ch*16 + 2*tig;
#pragma unroll
        for (int mt = 0; mt < 2; mt++) {
            int b0 = wm + mt*16 + grp, b1 = b0 + 8;
            unsigned ah0, al0, ah1, al1, ah2, al2, ah3, al3;
            split_pack(xval(xr,b0,kgA),   xval(xr,b0,kgA+1), ah0, al0);
            split_pack(xval(xr,b1,kgA),   xval(xr,b1,kgA+1), ah1, al1);
            split_pack(xval(xr,b0,kgA+8), xval(xr,b0,kgA+9), ah2, al2);
            split_pack(xval(xr,b1,kgA+8), xval(xr,b1,kgA+9), ah3, al3);
#pragma unroll
            for (int nt = 0; nt < 2; nt++) {
                mma_bf16(acc[mt][nt][0], acc[mt][nt][1], acc[mt][nt][2], acc[mt][nt][3],
                         ah0, ah1, ah2, ah3, bh[nt][0], bh[nt][1]);
                mma_bf16(acc[mt][nt][0], acc[mt][nt][1], acc[mt][nt][2], acc[mt][nt][3],
                         ah0, ah1, ah2, ah3, bl[nt][0], bl[nt][1]);
                mma_bf16(acc[mt][nt][0], acc[mt][nt][1], acc[mt][nt][2], acc[mt][nt][3],
                         al0, al1, al2, al3, bh[nt][0], bh[nt][1]);
            }
        }
        __syncthreads();
    }

    float* zh = xraw;
    int n = n0 + nd;
#pragma unroll
    for (int mt = 0; mt < 2; mt++) {
#pragma unroll
        for (int nt = 0; nt < 2; nt++) {
            int o0 = wn + nt*8 + tig*2;
#pragma unroll
            for (int c = 0; c < 4; c++) {
                int b = wm + mt*16 + grp + ((c >> 1) ? 8 : 0);
                int o = o0 + (c & 1);
                float hc = tanhf(acc[mt][nt][c] + sbias[nd*64 + o]);
                size_t idx = (size_t)(n*BB + b)*HH + o;
                float hv = d_h[idx];
                float rv = d_r[idx];
                float hn = rv*hv + (1.f - rv)*hc;
                d_h[idx] = hn;
                out[((size_t)(b*TT + t)*NN + n)*HH + o] = hn;
                zh[nd*4096 + b*64 + o] = hn;
            }
        }
    }
    __syncthreads();

    if (t + 1 < TT) {
        unsigned* Xgh = (unsigned*)d_Xg;
        unsigned* Xgl = Xgh + (size_t)NP2*LCOLS;
        for (int idx = tid; idx < 4096; idx += 512) {
            int b = idx >> 6, o = idx & 63;
            unsigned h, l;
            split_pack(zh[idx], zh[4096 + idx], h, l);
            Xgh[(size_t)ip*LCOLS + b*CC + 1 + o] = h;
            Xgl[(size_t)ip*LCOLS + b*CC + 1 + o] = l;
        }
        if (tid < 64) {
            unsigned h, l;
            split_pack(x[(size_t)(tid*TT + t+1)*NN + n0], x[(size_t)(tid*TT + t+1)*NN + n0 + 1], h, l);
            Xgh[(size_t)ip*LCOLS + tid*CC] = h;
            Xgl[(size_t)ip*LCOLS + tid*CC] = l;
        }
    }
}

// ---------------- host launcher ----------------
extern "C" void kernel_launch(void* const* d_in, const int* in_sizes, int n_in,
                              void* d_out, int out_size)
{
    const float *x = nullptr, *nodeE = nullptr, *timeE = nullptr;
    const float *gW = nullptr, *gb = nullptr, *uW = nullptr, *ub = nullptr;
    const float *ln16[4] = {nullptr, nullptr, nullptr, nullptr};
    int nln = 0;
    for (int i = 0; i < n_in; i++) {
        const float* p = (const float*)d_in[i];
        switch (in_sizes[i]) {
            case 786432: x = p; break;      // [64,12,1024,1]
            case 16384:  nodeE = p; break;  // [1024,16]
            case 192:    timeE = p; break;  // [12,16]
            case 399360: gW = p; break;     // [16,3,65,128]
            case 2048:   gb = p; break;     // [16,128]
            case 199680: uW = p; break;     // [16,3,65,64]
            case 1024:   ub = p; break;     // [16,64]
            case 16:     if (nln < 4) ln16[nln++] = p; break;
            default: break;
        }
    }
    const float* glg = ln16[0]; const float* glb = ln16[1];
    const float* ulg = ln16[2]; const float* ulb = ln16[3];
    float* out = (float*)d_out;

    cudaFuncSetAttribute(mma_gemm2,      cudaFuncAttributeMaxDynamicSharedMemorySize, GEMM_SMEM);
    cudaFuncSetAttribute(gate_epi_mma,   cudaFuncAttributeMaxDynamicSharedMemorySize, GATE_SMEM);
    cudaFuncSetAttribute(update_epi_mma, cudaFuncAttributeMaxDynamicSharedMemorySize, UPD_SMEM);

    zero_h_kernel<<<(NN*BB*HH + 255)/256, 256>>>();
    compute_ne_kernel<<<(TT*NN + 255)/256, 256>>>(nodeE, timeE, glg, glb, ulg, ulb);
    score_kernel<<<dim3(8, 8, 2*TT), 256>>>();
    softmax_kernel<<<dim3(128, TT, 2), 256>>>();
    pack0_kernel<<<((size_t)NP2*LCOLS + 255)/256, 256>>>(x);

    dim3 ggrid((LCOLS + 255)/256, NN/128);   // (17, 8) = 136 blocks
    for (int t = 0; t < TT; t++) {
        wgen_gate<<<NN/8, 256>>>(gW, t);
        wgen_update<<<NN/8, 256>>>(uW, t);
        mma_gemm2<<<ggrid, 256, GEMM_SMEM>>>(0, t, 0, 1);   // Y1g = Sg @ Xg
        mma_gemm2<<<ggrid, 256, GEMM_SMEM>>>(0, t, 1, 2);   // Y2g = Sg @ Y1g
        gate_epi_mma<<<NN/2, 512, GATE_SMEM>>>(gb, x, t);
        mma_gemm2<<<ggrid, 256, GEMM_SMEM>>>(1, t, 3, 4);   // Y1u = Su @ Xu
        mma_gemm2<<<ggrid, 256, GEMM_SMEM>>>(1, t, 4, 5);   // Y2u = Su @ Y1u
        update_epi_mma<<<NN/2, 512, UPD_SMEM>>>(ub, out, x, t);
    }
}